// round 10
// baseline (speedup 1.0000x reference)
#include <cuda_runtime.h>
#include <cstdint>

#define CIN  256
#define CI   128
#define NPIX 4096
#define BATCH 8

// Scratch. theta/phi stored PRE-SPLIT as packed bf16x2 hi/lo, [n][64 pairs].
// g stored tf32-prequantized channel-major. att n-major.
__device__ uint32_t g_qh[BATCH][NPIX][64];
__device__ uint32_t g_ql[BATCH][NPIX][64];
__device__ uint32_t g_kh[BATCH][NPIX][64];
__device__ uint32_t g_kl[BATCH][NPIX][64];
__device__ float    g_v [BATCH][CI][NPIX];
__device__ float    g_att[BATCH][NPIX][CI];

// ---- packed f32x2 helpers (proj / wconv) ----
__device__ __forceinline__ unsigned long long pk2(float lo, float hi) {
    unsigned long long r; asm("mov.b64 %0,{%1,%2};" : "=l"(r) : "f"(lo), "f"(hi)); return r;
}
__device__ __forceinline__ void upk2(unsigned long long v, float& lo, float& hi) {
    asm("mov.b64 {%0,%1},%2;" : "=f"(lo), "=f"(hi) : "l"(v));
}
__device__ __forceinline__ unsigned long long ffma2(unsigned long long a,
    unsigned long long b, unsigned long long c) {
    unsigned long long d;
    asm("fma.rn.f32x2 %0,%1,%2,%3;" : "=l"(d) : "l"(a), "l"(b), "l"(c)); return d;
}

// ---- mma.sync helpers ----
__device__ __forceinline__ uint32_t tf32r(float f) {
    uint32_t u; asm("cvt.rna.tf32.f32 %0,%1;" : "=r"(u) : "f"(f)); return u;
}
__device__ __forceinline__ void mma8(float* d, const uint32_t* a, const uint32_t* b) {
    asm volatile("mma.sync.aligned.m16n8k8.row.col.f32.tf32.tf32.f32 "
        "{%0,%1,%2,%3}, {%4,%5,%6,%7}, {%8,%9}, {%0,%1,%2,%3};"
        : "+f"(d[0]), "+f"(d[1]), "+f"(d[2]), "+f"(d[3])
        : "r"(a[0]), "r"(a[1]), "r"(a[2]), "r"(a[3]), "r"(b[0]), "r"(b[1]));
}
__device__ __forceinline__ void mma16(float* d, const uint32_t* a, const uint32_t* b) {
    asm volatile("mma.sync.aligned.m16n8k16.row.col.f32.bf16.bf16.f32 "
        "{%0,%1,%2,%3}, {%4,%5,%6,%7}, {%8,%9}, {%0,%1,%2,%3};"
        : "+f"(d[0]), "+f"(d[1]), "+f"(d[2]), "+f"(d[3])
        : "r"(a[0]), "r"(a[1]), "r"(a[2]), "r"(a[3]), "r"(b[0]), "r"(b[1]));
}
// pack two floats to bf16x2 {lo half = x, hi half = y}
__device__ __forceinline__ uint32_t bfp2(float x, float y) {
    uint32_t r; asm("cvt.rn.bf16x2.f32 %0,%1,%2;" : "=r"(r) : "f"(y), "f"(x)); return r;
}
// cp.async 16B
__device__ __forceinline__ void cpa16(uint32_t saddr, const void* gaddr) {
    asm volatile("cp.async.cg.shared.global [%0],[%1],16;" :: "r"(saddr), "l"(gaddr));
}
#define CP_COMMIT() asm volatile("cp.async.commit_group;" ::: "memory")
#define CP_WAIT0()  asm volatile("cp.async.wait_group 0;" ::: "memory")

// fast exp(s-30) on FMA pipe, tf32-truncated
__device__ __forceinline__ float pexp30(float s) {
    float y = fmaf(s, 1.44269504f, -43.28085123f);
    int ei = __float2int_rn(y);
    float f = y - (float)ei;
    float pl = fmaf(f, 1.3333558e-3f, 9.6181291e-3f);
    pl = fmaf(f, pl, 5.5504109e-2f);
    pl = fmaf(f, pl, 2.4022651e-1f);
    pl = fmaf(f, pl, 6.9314718e-1f);
    pl = fmaf(f, pl, 1.0f);
    int e2 = ei + 127;
    e2 = e2 < 0 ? 0 : (e2 > 254 ? 254 : e2);
    float p = pl * __int_as_float(e2 << 23);
    return __uint_as_float(tf32r(p));
}

// ============================================================================
// Kernel 1: fused QKV projection (unchanged).
// ============================================================================
__global__ __launch_bounds__(256) void proj_kernel(
    const float* __restrict__ x,
    const float* __restrict__ tw, const float* __restrict__ tb,
    const float* __restrict__ pw, const float* __restrict__ pb,
    const float* __restrict__ gw, const float* __restrict__ gb)
{
    __shared__ float ws[CI][33];
    __shared__ float xs[32][64];
    const int b = blockIdx.z, pj = blockIdx.y, n0g = blockIdx.x * 64;
    const float* w    = (pj == 0) ? tw : (pj == 1) ? pw : gw;
    const float* bias = (pj == 0) ? tb : (pj == 1) ? pb : gb;
    const int tid = threadIdx.x, tx = tid & 15, ty = tid >> 4;
    const int n0 = tx * 4, co0 = ty * 8;

    unsigned long long acc[8][2];
    #pragma unroll
    for (int o = 0; o < 8; o++) { float bv = bias[co0 + o]; acc[o][0] = acc[o][1] = pk2(bv, bv); }
    const float* xb = x + (size_t)b * CIN * NPIX;

    for (int c0 = 0; c0 < CIN; c0 += 32) {
        __syncthreads();
        #pragma unroll
        for (int k = 0; k < 16; k++) {
            int idx = tid + k * 256, co = idx >> 5, cc = idx & 31;
            ws[co][cc] = w[co * CIN + c0 + cc];
        }
        #pragma unroll
        for (int k = 0; k < 2; k++) {
            int id = tid + k * 256, cc = id >> 4, n4 = id & 15;
            *(float4*)&xs[cc][n4 * 4] =
                *(const float4*)&xb[(size_t)(c0 + cc) * NPIX + n0g + n4 * 4];
        }
        __syncthreads();
        #pragma unroll
        for (int cc = 0; cc < 32; cc++) {
            ulonglong2 xv = *(ulonglong2*)&xs[cc][n0];
            #pragma unroll
            for (int o = 0; o < 8; o++) {
                unsigned long long w2 = pk2(ws[co0 + o][cc], ws[co0 + o][cc]);
                acc[o][0] = ffma2(w2, xv.x, acc[o][0]);
                acc[o][1] = ffma2(w2, xv.y, acc[o][1]);
            }
        }
    }
    if (pj <= 1) {
        float v[8][4];
        #pragma unroll
        for (int o = 0; o < 8; o++) { upk2(acc[o][0], v[o][0], v[o][1]); upk2(acc[o][1], v[o][2], v[o][3]); }
        uint32_t* ph = (pj == 0) ? &g_qh[b][0][0] : &g_kh[b][0][0];
        uint32_t* pl = (pj == 0) ? &g_ql[b][0][0] : &g_kl[b][0][0];
        #pragma unroll
        for (int r = 0; r < 4; r++) {
            uint32_t hp[4], lp[4];
            #pragma unroll
            for (int pp = 0; pp < 4; pp++) {
                float a = v[2 * pp][r], c = v[2 * pp + 1][r];
                uint32_t h = bfp2(a, c);
                float hx = __uint_as_float(h << 16);
                float hy = __uint_as_float(h & 0xFFFF0000u);
                hp[pp] = h;
                lp[pp] = bfp2(a - hx, c - hy);
            }
            size_t row = (size_t)(n0g + n0 + r) * 64 + (co0 >> 1);
            *(uint4*)&ph[row] = make_uint4(hp[0], hp[1], hp[2], hp[3]);
            *(uint4*)&pl[row] = make_uint4(lp[0], lp[1], lp[2], lp[3]);
        }
    } else {
        float* outp = &g_v[b][0][0];
        #pragma unroll
        for (int o = 0; o < 8; o++) {
            float4 r; upk2(acc[o][0], r.x, r.y); upk2(acc[o][1], r.z, r.w);
            float4 t = { __uint_as_float(tf32r(r.x)), __uint_as_float(tf32r(r.y)),
                         __uint_as_float(tf32r(r.z)), __uint_as_float(tf32r(r.w)) };
            *(float4*)&outp[(size_t)(co0 + o) * NPIX + n0g + n0] = t;
        }
    }
}

// ============================================================================
// Kernel 2: attention, split-j.  512 threads / 16 warps: warp w handles rows
// (w&7)*16..+16 and j-half (w>>3)*32..+32.  Cross-half O/l reduction at end.
// ============================================================================
#define QP_STRIDE 68
#define SM_QH 0
#define SM_QL (128 * QP_STRIDE)                        //  8704
#define SM_ST (2 * 128 * QP_STRIDE)                    // 17408
#define STG   (2 * 64 * QP_STRIDE + 128 * QP_STRIDE)   // 17408 u32 / stage
#define ATTN_SMEM_W (SM_ST + 2 * STG)                  // 52224 u32 = 208896 B

__global__ __launch_bounds__(512, 1) void attn_mma_kernel()
{
    extern __shared__ uint32_t smw[];
    uint32_t* Qh2 = smw + SM_QH;
    uint32_t* Ql2 = smw + SM_QL;
    const uint32_t smb = (uint32_t)__cvta_generic_to_shared(smw);

    const int tid = threadIdx.x, wid = tid >> 5, lane = tid & 31;
    const int g = lane >> 2, q = lane & 3;
    const int b = blockIdx.y, i0g = blockIdx.x * 128;
    const int wr = wid & 7, jh = wid >> 3;
    const int iw = wr * 16, j0h = jh * 32;

    // prefetch tile 0 into stage 0
    {
        const uint32_t base = smb + 4u * SM_ST;
        const uint32_t* sKh = &g_kh[b][0][0];
        const uint32_t* sKl = &g_kl[b][0][0];
        const float*    sV  = &g_v[b][0][0];
        #pragma unroll
        for (int v = 0; v < 2; v++) {
            int id = tid + v * 512, j = id >> 4, ch = (id & 15) * 4;
            cpa16(base + 4u * (j * QP_STRIDE + ch), sKh + j * 64 + ch);
        }
        #pragma unroll
        for (int v = 0; v < 2; v++) {
            int id = tid + v * 512, j = id >> 4, ch = (id & 15) * 4;
            cpa16(base + 4u * (64 * QP_STRIDE + j * QP_STRIDE + ch), sKl + j * 64 + ch);
        }
        #pragma unroll
        for (int v = 0; v < 4; v++) {
            int id = tid + v * 512, c = id >> 4, ch = (id & 15) * 4;
            cpa16(base + 4u * (128 * QP_STRIDE + c * QP_STRIDE + ch), sV + (size_t)c * NPIX + ch);
        }
        CP_COMMIT();
    }

    // Q tiles (once)
    {
        const uint32_t* sQh = &g_qh[b][i0g][0];
        const uint32_t* sQl = &g_ql[b][i0g][0];
        #pragma unroll
        for (int v = 0; v < 4; v++) {
            int id = tid + v * 512, i = id >> 4, ch = (id & 15) * 4;
            *(uint4*)&Qh2[i * QP_STRIDE + ch] = *(const uint4*)&sQh[i * 64 + ch];
            *(uint4*)&Ql2[i * QP_STRIDE + ch] = *(const uint4*)&sQl[i * 64 + ch];
        }
    }

    float o[16][4];
    #pragma unroll
    for (int n = 0; n < 16; n++)
        #pragma unroll
        for (int r = 0; r < 4; r++) o[n][r] = 0.f;
    float ls0 = 0.f, ls1 = 0.f;

    for (int t = 0; t < 64; t++) {
        const int s = t & 1;
        CP_WAIT0();
        __syncthreads();

        if (t < 63) {
            const int j1 = (t + 1) * 64;
            const uint32_t base = smb + 4u * (SM_ST + (s ^ 1) * STG);
            const uint32_t* sKh = &g_kh[b][j1][0];
            const uint32_t* sKl = &g_kl[b][j1][0];
            const float*    sV  = &g_v[b][0][j1];
            #pragma unroll
            for (int v = 0; v < 2; v++) {
                int id = tid + v * 512, j = id >> 4, ch = (id & 15) * 4;
                cpa16(base + 4u * (j * QP_STRIDE + ch), sKh + j * 64 + ch);
            }
            #pragma unroll
            for (int v = 0; v < 2; v++) {
                int id = tid + v * 512, j = id >> 4, ch = (id & 15) * 4;
                cpa16(base + 4u * (64 * QP_STRIDE + j * QP_STRIDE + ch), sKl + j * 64 + ch);
            }
            #pragma unroll
            for (int v = 0; v < 4; v++) {
                int id = tid + v * 512, c = id >> 4, ch = (id & 15) * 4;
                cpa16(base + 4u * (128 * QP_STRIDE + c * QP_STRIDE + ch), sV + (size_t)c * NPIX + ch);
            }
            CP_COMMIT();
        }

        uint32_t* Kh2 = smw + SM_ST + s * STG;
        uint32_t* Kl2 = Kh2 + 64 * QP_STRIDE;
        float*    Vs  = (float*)(Kh2 + 128 * QP_STRIDE);

        // ---- S = Q K^T on this warp's j-half ----
        float ds[4][4];
        #pragma unroll
        for (int n = 0; n < 4; n++)
            #pragma unroll
            for (int r = 0; r < 4; r++) ds[n][r] = 0.f;

        #pragma unroll
        for (int kc = 0; kc < 8; kc++) {
            const int kp = kc * 8;
            const int ra = (iw + g) * QP_STRIDE + kp + q;
            const int rb = (iw + g + 8) * QP_STRIDE + kp + q;
            uint32_t ah[4] = { Qh2[ra], Qh2[rb], Qh2[ra + 4], Qh2[rb + 4] };
            uint32_t al[4] = { Ql2[ra], Ql2[rb], Ql2[ra + 4], Ql2[rb + 4] };
            #pragma unroll
            for (int n = 0; n < 4; n++) {
                const int kb = (j0h + n * 8 + g) * QP_STRIDE + kp + q;
                uint32_t bh[2] = { Kh2[kb], Kh2[kb + 4] };
                uint32_t bl[2] = { Kl2[kb], Kl2[kb + 4] };
                mma16(ds[n], ah, bh);
                mma16(ds[n], ah, bl);
                mma16(ds[n], al, bh);
            }
        }

        // ---- P = exp(S-30) tf32; partial l ----
        #pragma unroll
        for (int n = 0; n < 4; n++) {
            float p0 = pexp30(ds[n][0]), p1 = pexp30(ds[n][1]);
            float p2 = pexp30(ds[n][2]), p3 = pexp30(ds[n][3]);
            ds[n][0] = p0; ds[n][1] = p1; ds[n][2] = p2; ds[n][3] = p3;
            ls0 += p0 + p1;
            ls1 += p2 + p3;
        }

        // ---- O += P V^T over this warp's 32 j's ----
        const int csel = q & 1;
        const int src1 = (lane & ~3) | (q >> 1);
        const int src2 = src1 + 2;
        #pragma unroll
        for (int jk = 0; jk < 4; jk++) {
            float t0 = __shfl_sync(0xffffffffu, ds[jk][0], src1);
            float t1 = __shfl_sync(0xffffffffu, ds[jk][1], src1);
            float t2 = __shfl_sync(0xffffffffu, ds[jk][2], src1);
            float t3 = __shfl_sync(0xffffffffu, ds[jk][3], src1);
            float u0 = __shfl_sync(0xffffffffu, ds[jk][0], src2);
            float u1 = __shfl_sync(0xffffffffu, ds[jk][1], src2);
            float u2 = __shfl_sync(0xffffffffu, ds[jk][2], src2);
            float u3 = __shfl_sync(0xffffffffu, ds[jk][3], src2);
            uint32_t pa[4] = { __float_as_uint(csel ? t1 : t0),
                               __float_as_uint(csel ? t3 : t2),
                               __float_as_uint(csel ? u1 : u0),
                               __float_as_uint(csel ? u3 : u2) };
            const int jb = j0h + jk * 8;
            #pragma unroll
            for (int nc = 0; nc < 16; nc++) {
                uint32_t vb[2] = { __float_as_uint(Vs[(nc * 8 + g) * QP_STRIDE + jb + q]),
                                   __float_as_uint(Vs[(nc * 8 + g) * QP_STRIDE + jb + q + 4]) };
                mma8(o[nc], pa, vb);
            }
        }
    }

    // ---- row sums within this half ----
    ls0 += __shfl_xor_sync(0xffffffffu, ls0, 1);
    ls0 += __shfl_xor_sync(0xffffffffu, ls0, 2);
    ls1 += __shfl_xor_sync(0xffffffffu, ls1, 1);
    ls1 += __shfl_xor_sync(0xffffffffu, ls1, 2);

    // ---- cross-half reduction (reuse stage smem; Q area for l) ----
    __syncthreads();
    float* ored  = (float*)(smw + SM_ST);      // [256][68] padded
    float* lred0 = (float*)(smw + SM_QH);      // 256
    float* lred1 = lred0 + 256;
    const int tslot = wr * 32 + lane;
    if (jh == 1) {
        #pragma unroll
        for (int nc = 0; nc < 16; nc++)
            *(float4*)&ored[tslot * 68 + nc * 4] = *(float4*)&o[nc][0];
        lred0[tslot] = ls0;
        lred1[tslot] = ls1;
    }
    __syncthreads();
    if (jh == 0) {
        const float inv0 = 1.f / (ls0 + lred0[tslot]);
        const float inv1 = 1.f / (ls1 + lred1[tslot]);
        const int r0 = i0g + iw + g, r1 = r0 + 8;
        #pragma unroll
        for (int nc = 0; nc < 16; nc++) {
            float4 p = *(float4*)&ored[tslot * 68 + nc * 4];
            const int cc = nc * 8 + 2 * q;
            *(float2*)&g_att[b][r0][cc] =
                make_float2((o[nc][0] + p.x) * inv0, (o[nc][1] + p.y) * inv0);
            *(float2*)&g_att[b][r1][cc] =
                make_float2((o[nc][2] + p.z) * inv1, (o[nc][3] + p.w) * inv1);
        }
    }
}

// ============================================================================
// Kernel 3: W conv + bias + residual (unchanged).
// ============================================================================
__global__ __launch_bounds__(256) void wconv_kernel(
    const float* __restrict__ x, const float* __restrict__ Ww,
    const float* __restrict__ Wb, float* __restrict__ out)
{
    __shared__ float ws2[64][33];
    __shared__ float as[32][68];
    const int b = blockIdx.z, og0 = blockIdx.y * 64, gn0 = blockIdx.x * 64;
    const int tid = threadIdx.x, tx = tid & 15, ty = tid >> 4;
    const int n0 = tx * 4, o0 = ty * 4;

    unsigned long long acc[4][2];
    #pragma unroll
    for (int o = 0; o < 4; o++) { float bv = Wb[og0 + o0 + o]; acc[o][0] = acc[o][1] = pk2(bv, bv); }
    const float* attb = &g_att[b][0][0];

    for (int c0 = 0; c0 < CI; c0 += 32) {
        __syncthreads();
        #pragma unroll
        for (int k = 0; k < 8; k++) {
            int idx = tid + k * 256, o = idx >> 5, cc = idx & 31;
            ws2[o][cc] = Ww[(og0 + o) * CI + c0 + cc];
        }
        #pragma unroll
        for (int k = 0; k < 2; k++) {
            int id = tid + k * 256, n = id >> 3, c4 = id & 7;
            float4 v = *(const float4*)&attb[(size_t)(gn0 + n) * CI + c0 + c4 * 4];
            as[c4*4+0][n] = v.x; as[c4*4+1][n] = v.y; as[c4*4+2][n] = v.z; as[c4*4+3][n] = v.w;
        }
        __syncthreads();
        #pragma unroll
        for (int cc = 0; cc < 32; cc++) {
            ulonglong2 av = *(ulonglong2*)&as[cc][n0];
            #pragma unroll
            for (int o = 0; o < 4; o++) {
                unsigned long long w2 = pk2(ws2[o0 + o][cc], ws2[o0 + o][cc]);
                acc[o][0] = ffma2(w2, av.x, acc[o][0]);
                acc[o][1] = ffma2(w2, av.y, acc[o][1]);
            }
        }
    }
    #pragma unroll
    for (int o = 0; o < 4; o++) {
        float4 r; upk2(acc[o][0], r.x, r.y); upk2(acc[o][1], r.z, r.w);
        size_t off = ((size_t)b * CIN + og0 + o0 + o) * NPIX + gn0 + n0;
        float4 xv = *(const float4*)&x[off];
        r.x += xv.x; r.y += xv.y; r.z += xv.z; r.w += xv.w;
        *(float4*)&out[off] = r;
    }
}

// ============================================================================
extern "C" void kernel_launch(void* const* d_in, const int* in_sizes, int n_in,
                              void* d_out, int out_size)
{
    const float* x    = (const float*)d_in[0];
    const float* g_w  = (const float*)d_in[1];
    const float* g_b  = (const float*)d_in[2];
    const float* th_w = (const float*)d_in[3];
    const float* th_b = (const float*)d_in[4];
    const float* ph_w = (const float*)d_in[5];
    const float* ph_b = (const float*)d_in[6];
    const float* W_w  = (const float*)d_in[7];
    const float* W_b  = (const float*)d_in[8];
    float* out = (float*)d_out;

    proj_kernel<<<dim3(64, 3, 8), 256>>>(x, th_w, th_b, ph_w, ph_b, g_w, g_b);

    const int attn_smem = ATTN_SMEM_W * 4;   // 208896 B
    cudaFuncSetAttribute(attn_mma_kernel,
                         cudaFuncAttributeMaxDynamicSharedMemorySize, attn_smem);
    attn_mma_kernel<<<dim3(32, 8), 512, attn_smem>>>();

    wconv_kernel<<<dim3(64, 4, 8), 256>>>(x, W_w, W_b, out);
}

// round 11
// speedup vs baseline: 1.1811x; 1.1811x over previous
#include <cuda_runtime.h>
#include <cstdint>

#define CIN  256
#define CI   128
#define NPIX 4096
#define BATCH 8

// Scratch. theta/phi PRE-SPLIT packed bf16x2 hi/lo [n][64 pairs]; g tf32 [c][n];
// att n-major. Weights pre-split by prep_kernel.
__device__ uint32_t g_qh[BATCH][NPIX][64];
__device__ uint32_t g_ql[BATCH][NPIX][64];
__device__ uint32_t g_kh[BATCH][NPIX][64];
__device__ uint32_t g_kl[BATCH][NPIX][64];
__device__ float    g_v [BATCH][CI][NPIX];
__device__ float    g_att[BATCH][NPIX][CI];
__device__ uint32_t g_wh[3][CI][128];     // proj weights, pairs over cin
__device__ uint32_t g_wl[3][CI][128];
__device__ uint32_t g_WWh[CIN][64];       // W conv weights, pairs over ci
__device__ uint32_t g_WWl[CIN][64];

// ---- mma.sync helpers ----
__device__ __forceinline__ uint32_t tf32r(float f) {
    uint32_t u; asm("cvt.rna.tf32.f32 %0,%1;" : "=r"(u) : "f"(f)); return u;
}
__device__ __forceinline__ void mma8(float* d, const uint32_t* a, const uint32_t* b) {
    asm volatile("mma.sync.aligned.m16n8k8.row.col.f32.tf32.tf32.f32 "
        "{%0,%1,%2,%3}, {%4,%5,%6,%7}, {%8,%9}, {%0,%1,%2,%3};"
        : "+f"(d[0]), "+f"(d[1]), "+f"(d[2]), "+f"(d[3])
        : "r"(a[0]), "r"(a[1]), "r"(a[2]), "r"(a[3]), "r"(b[0]), "r"(b[1]));
}
__device__ __forceinline__ void mma16(float* d, const uint32_t* a, const uint32_t* b) {
    asm volatile("mma.sync.aligned.m16n8k16.row.col.f32.bf16.bf16.f32 "
        "{%0,%1,%2,%3}, {%4,%5,%6,%7}, {%8,%9}, {%0,%1,%2,%3};"
        : "+f"(d[0]), "+f"(d[1]), "+f"(d[2]), "+f"(d[3])
        : "r"(a[0]), "r"(a[1]), "r"(a[2]), "r"(a[3]), "r"(b[0]), "r"(b[1]));
}
// pack two floats to bf16x2 {lo half = x, hi half = y}
__device__ __forceinline__ uint32_t bfp2(float x, float y) {
    uint32_t r; asm("cvt.rn.bf16x2.f32 %0,%1,%2;" : "=r"(r) : "f"(y), "f"(x)); return r;
}
__device__ __forceinline__ float blo(uint32_t h) { return __uint_as_float(h << 16); }
__device__ __forceinline__ float bhi(uint32_t h) { return __uint_as_float(h & 0xFFFF0000u); }
// cp.async 16B
__device__ __forceinline__ void cpa16(uint32_t saddr, const void* gaddr) {
    asm volatile("cp.async.cg.shared.global [%0],[%1],16;" :: "r"(saddr), "l"(gaddr));
}
#define CP_COMMIT() asm volatile("cp.async.commit_group;" ::: "memory")
#define CP_WAIT0()  asm volatile("cp.async.wait_group 0;" ::: "memory")

// fast exp(s-30) on FMA pipe, tf32-truncated
__device__ __forceinline__ float pexp30(float s) {
    float y = fmaf(s, 1.44269504f, -43.28085123f);
    int ei = __float2int_rn(y);
    float f = y - (float)ei;
    float pl = fmaf(f, 1.3333558e-3f, 9.6181291e-3f);
    pl = fmaf(f, pl, 5.5504109e-2f);
    pl = fmaf(f, pl, 2.4022651e-1f);
    pl = fmaf(f, pl, 6.9314718e-1f);
    pl = fmaf(f, pl, 1.0f);
    int e2 = ei + 127;
    e2 = e2 < 0 ? 0 : (e2 > 254 ? 254 : e2);
    float p = pl * __int_as_float(e2 << 23);
    return __uint_as_float(tf32r(p));
}

// ============================================================================
// Kernel 0: weight prep — split all weights into packed bf16x2 hi/lo once.
// 64 blocks x 256 threads; gid in [0,16384).
// ============================================================================
__global__ __launch_bounds__(256) void prep_kernel(
    const float* __restrict__ tw, const float* __restrict__ pw,
    const float* __restrict__ gw, const float* __restrict__ Ww)
{
    const int gid = blockIdx.x * 256 + threadIdx.x;
    const float* ws[3] = { tw, pw, gw };
    const int co = gid >> 7, pr = gid & 127;
    #pragma unroll
    for (int pj = 0; pj < 3; pj++) {
        float a = ws[pj][co * CIN + 2 * pr], c = ws[pj][co * CIN + 2 * pr + 1];
        uint32_t h = bfp2(a, c);
        g_wh[pj][co][pr] = h;
        g_wl[pj][co][pr] = bfp2(a - blo(h), c - bhi(h));
    }
    {
        const int o = gid >> 6, p2 = gid & 63;
        float a = Ww[o * CI + 2 * p2], c = Ww[o * CI + 2 * p2 + 1];
        uint32_t h = bfp2(a, c);
        g_WWh[o][p2] = h;
        g_WWl[o][p2] = bfp2(a - blo(h), c - bhi(h));
    }
}

// ============================================================================
// Kernel 1: proj via bf16 3-term mma.  Block: [128 co x 64 n], K=256 (4 chunks).
// pj<=1: A=x rows n, B=w rows co -> D rows n, cols co (adjacent pair in thread).
// pj==2: A=w rows co, B=x rows n -> D rows co, cols n (direct [c][n] store).
// ============================================================================
#define PXR   0                       // x raw chunk [64 c][68] f32
#define PXPH  4352                    // x packed hi [64 n][36]
#define PXPL  (PXPH + 2304)
#define PWH   (PXPL + 2304)           // w packed hi [128 co][36]
#define PWL   (PWH + 4608)
#define PBS   (PWL + 4608)            // bias 128 f32
#define PROJ_SMEM_W (PBS + 128)       // 18304 u32 = 73216 B

__global__ __launch_bounds__(256) void proj_mma_kernel(
    const float* __restrict__ x,
    const float* __restrict__ tb, const float* __restrict__ pb,
    const float* __restrict__ gb)
{
    extern __shared__ uint32_t smu[];
    float*    xr  = (float*)(smu + PXR);
    uint32_t* xph = smu + PXPH;
    uint32_t* xpl = smu + PXPL;
    uint32_t* wh  = smu + PWH;
    uint32_t* wl  = smu + PWL;
    float*    bs  = (float*)(smu + PBS);

    const int b = blockIdx.z, pj = blockIdx.y, n0g = blockIdx.x * 64;
    const int tid = threadIdx.x, wid = tid >> 5, lane = tid & 31;
    const int g = lane >> 2, q = lane & 3;
    const float* bias = (pj == 0) ? tb : (pj == 1) ? pb : gb;
    if (tid < 128) bs[tid] = bias[tid];

    const float* xb = x + (size_t)b * CIN * NPIX;
    const uint32_t* wsh = &g_wh[pj][0][0];
    const uint32_t* wsl = &g_wl[pj][0][0];

    float ds[8][4];
    #pragma unroll
    for (int n = 0; n < 8; n++)
        #pragma unroll
        for (int r = 0; r < 4; r++) ds[n][r] = 0.f;

    for (int ck = 0; ck < 4; ck++) {
        const int c0 = ck * 64;
        __syncthreads();
        // x chunk [64 c][64 n] raw
        #pragma unroll
        for (int v = 0; v < 4; v++) {
            int id = tid + v * 256, cc = id >> 4, n4 = (id & 15) * 4;
            *(float4*)&xr[cc * 68 + n4] =
                *(const float4*)&xb[(size_t)(c0 + cc) * NPIX + n0g + n4];
        }
        // w chunk [128 co][32 pairs] hi/lo
        #pragma unroll
        for (int v = 0; v < 4; v++) {
            int id = tid + v * 256, co = id >> 3, p4 = (id & 7) * 4;
            *(uint4*)&wh[co * 36 + p4] = *(const uint4*)&wsh[co * 128 + ck * 32 + p4];
            *(uint4*)&wl[co * 36 + p4] = *(const uint4*)&wsl[co * 128 + ck * 32 + p4];
        }
        __syncthreads();
        // pack x: transpose to [n][pair] bf16 hi/lo
        #pragma unroll
        for (int v = 0; v < 8; v++) {
            int id = tid + v * 256, n = id & 63, pc = id >> 6;   // pc 0..31
            float a = xr[(2 * pc) * 68 + n], c = xr[(2 * pc + 1) * 68 + n];
            uint32_t h = bfp2(a, c);
            xph[n * 36 + pc] = h;
            xpl[n * 36 + pc] = bfp2(a - blo(h), c - bhi(h));
        }
        __syncthreads();

        if (pj <= 1) {
            const int mt = wid & 3, ch = wid >> 2, ar = mt * 16;
            #pragma unroll
            for (int kc = 0; kc < 4; kc++) {
                const int kp = kc * 8;
                uint32_t ah[4] = { xph[(ar + g) * 36 + kp + q], xph[(ar + g + 8) * 36 + kp + q],
                                   xph[(ar + g) * 36 + kp + q + 4], xph[(ar + g + 8) * 36 + kp + q + 4] };
                uint32_t al[4] = { xpl[(ar + g) * 36 + kp + q], xpl[(ar + g + 8) * 36 + kp + q],
                                   xpl[(ar + g) * 36 + kp + q + 4], xpl[(ar + g + 8) * 36 + kp + q + 4] };
                #pragma unroll
                for (int nc = 0; nc < 8; nc++) {
                    const int br = (ch * 64 + nc * 8 + g) * 36 + kp;
                    uint32_t bh[2] = { wh[br + q], wh[br + q + 4] };
                    uint32_t bl[2] = { wl[br + q], wl[br + q + 4] };
                    mma16(ds[nc], ah, bh);
                    mma16(ds[nc], ah, bl);
                    mma16(ds[nc], al, bh);
                }
            }
        } else {
            const int ar = wid * 16;
            #pragma unroll
            for (int kc = 0; kc < 4; kc++) {
                const int kp = kc * 8;
                uint32_t ah[4] = { wh[(ar + g) * 36 + kp + q], wh[(ar + g + 8) * 36 + kp + q],
                                   wh[(ar + g) * 36 + kp + q + 4], wh[(ar + g + 8) * 36 + kp + q + 4] };
                uint32_t al[4] = { wl[(ar + g) * 36 + kp + q], wl[(ar + g + 8) * 36 + kp + q],
                                   wl[(ar + g) * 36 + kp + q + 4], wl[(ar + g + 8) * 36 + kp + q + 4] };
                #pragma unroll
                for (int nc = 0; nc < 8; nc++) {
                    const int br = (nc * 8 + g) * 36 + kp;
                    uint32_t bh[2] = { xph[br + q], xph[br + q + 4] };
                    uint32_t bl[2] = { xpl[br + q], xpl[br + q + 4] };
                    mma16(ds[nc], ah, bh);
                    mma16(ds[nc], ah, bl);
                    mma16(ds[nc], al, bh);
                }
            }
        }
    }

    if (pj <= 1) {
        uint32_t* ph = (pj == 0) ? &g_qh[b][0][0] : &g_kh[b][0][0];
        uint32_t* pl = (pj == 0) ? &g_ql[b][0][0] : &g_kl[b][0][0];
        const int mt = wid & 3, ch = wid >> 2;
        const int nr0 = n0g + mt * 16 + g, nr1 = nr0 + 8;
        #pragma unroll
        for (int nc = 0; nc < 8; nc++) {
            const int co0 = ch * 64 + nc * 8 + 2 * q;
            const float b0 = bs[co0], b1 = bs[co0 + 1];
            float v0 = ds[nc][0] + b0, v1 = ds[nc][1] + b1;
            float v2 = ds[nc][2] + b0, v3 = ds[nc][3] + b1;
            uint32_t h0 = bfp2(v0, v1), h1 = bfp2(v2, v3);
            uint32_t l0 = bfp2(v0 - blo(h0), v1 - bhi(h0));
            uint32_t l1 = bfp2(v2 - blo(h1), v3 - bhi(h1));
            const int pr = ch * 32 + nc * 4 + q;
            ph[(size_t)nr0 * 64 + pr] = h0;  pl[(size_t)nr0 * 64 + pr] = l0;
            ph[(size_t)nr1 * 64 + pr] = h1;  pl[(size_t)nr1 * 64 + pr] = l1;
        }
    } else {
        float* outp = &g_v[b][0][0];
        const int c0 = wid * 16 + g, c1 = c0 + 8;
        const float b0 = bs[c0], b1 = bs[c1];
        #pragma unroll
        for (int nc = 0; nc < 8; nc++) {
            const int n = n0g + nc * 8 + 2 * q;
            *(float2*)&outp[(size_t)c0 * NPIX + n] = make_float2(
                __uint_as_float(tf32r(ds[nc][0] + b0)), __uint_as_float(tf32r(ds[nc][1] + b0)));
            *(float2*)&outp[(size_t)c1 * NPIX + n] = make_float2(
                __uint_as_float(tf32r(ds[nc][2] + b1)), __uint_as_float(tf32r(ds[nc][3] + b1)));
        }
    }
}

// ============================================================================
// Kernel 2: attention (R9 exact — 256 threads, cp.async double-buffered).
// ============================================================================
#define QP_STRIDE 68
#define SM_QH 0
#define SM_QL (128 * QP_STRIDE)
#define SM_ST (2 * 128 * QP_STRIDE)
#define STG   (2 * 64 * QP_STRIDE + 128 * QP_STRIDE)
#define ATTN_SMEM_W (SM_ST + 2 * STG)            // 52224 u32 = 208896 B

__global__ __launch_bounds__(256, 1) void attn_mma_kernel()
{
    extern __shared__ uint32_t smw[];
    uint32_t* Qh2 = smw + SM_QH;
    uint32_t* Ql2 = smw + SM_QL;
    const uint32_t smb = (uint32_t)__cvta_generic_to_shared(smw);

    const int tid = threadIdx.x, wid = tid >> 5, lane = tid & 31;
    const int g = lane >> 2, q = lane & 3;
    const int b = blockIdx.y, i0g = blockIdx.x * 128;
    const int iw = wid * 16;

    {
        const uint32_t base = smb + 4u * SM_ST;
        const uint32_t* sKh = &g_kh[b][0][0];
        const uint32_t* sKl = &g_kl[b][0][0];
        const float*    sV  = &g_v[b][0][0];
        #pragma unroll
        for (int v = 0; v < 4; v++) {
            int id = tid + v * 256, j = id >> 4, ch = (id & 15) * 4;
            cpa16(base + 4u * (j * QP_STRIDE + ch), sKh + j * 64 + ch);
        }
        #pragma unroll
        for (int v = 0; v < 4; v++) {
            int id = tid + v * 256, j = id >> 4, ch = (id & 15) * 4;
            cpa16(base + 4u * (64 * QP_STRIDE + j * QP_STRIDE + ch), sKl + j * 64 + ch);
        }
        #pragma unroll
        for (int v = 0; v < 8; v++) {
            int id = tid + v * 256, c = id >> 4, ch = (id & 15) * 4;
            cpa16(base + 4u * (128 * QP_STRIDE + c * QP_STRIDE + ch), sV + (size_t)c * NPIX + ch);
        }
        CP_COMMIT();
    }
    {
        const uint32_t* sQh = &g_qh[b][i0g][0];
        const uint32_t* sQl = &g_ql[b][i0g][0];
        #pragma unroll
        for (int v = 0; v < 8; v++) {
            int id = tid + v * 256, i = id >> 4, ch = (id & 15) * 4;
            *(uint4*)&Qh2[i * QP_STRIDE + ch] = *(const uint4*)&sQh[i * 64 + ch];
            *(uint4*)&Ql2[i * QP_STRIDE + ch] = *(const uint4*)&sQl[i * 64 + ch];
        }
    }

    float o[16][4];
    #pragma unroll
    for (int n = 0; n < 16; n++)
        #pragma unroll
        for (int r = 0; r < 4; r++) o[n][r] = 0.f;
    float ls0 = 0.f, ls1 = 0.f;

    for (int t = 0; t < 64; t++) {
        const int s = t & 1;
        CP_WAIT0();
        __syncthreads();

        if (t < 63) {
            const int j1 = (t + 1) * 64;
            const uint32_t base = smb + 4u * (SM_ST + (s ^ 1) * STG);
            const uint32_t* sKh = &g_kh[b][j1][0];
            const uint32_t* sKl = &g_kl[b][j1][0];
            const float*    sV  = &g_v[b][0][j1];
            #pragma unroll
            for (int v = 0; v < 4; v++) {
                int id = tid + v * 256, j = id >> 4, ch = (id & 15) * 4;
                cpa16(base + 4u * (j * QP_STRIDE + ch), sKh + j * 64 + ch);
            }
            #pragma unroll
            for (int v = 0; v < 4; v++) {
                int id = tid + v * 256, j = id >> 4, ch = (id & 15) * 4;
                cpa16(base + 4u * (64 * QP_STRIDE + j * QP_STRIDE + ch), sKl + j * 64 + ch);
            }
            #pragma unroll
            for (int v = 0; v < 8; v++) {
                int id = tid + v * 256, c = id >> 4, ch = (id & 15) * 4;
                cpa16(base + 4u * (128 * QP_STRIDE + c * QP_STRIDE + ch), sV + (size_t)c * NPIX + ch);
            }
            CP_COMMIT();
        }

        uint32_t* Kh2 = smw + SM_ST + s * STG;
        uint32_t* Kl2 = Kh2 + 64 * QP_STRIDE;
        float*    Vs  = (float*)(Kh2 + 128 * QP_STRIDE);

        float ds[8][4];
        #pragma unroll
        for (int n = 0; n < 8; n++)
            #pragma unroll
            for (int r = 0; r < 4; r++) ds[n][r] = 0.f;

        #pragma unroll
        for (int kc = 0; kc < 8; kc++) {
            const int kp = kc * 8;
            const int ra = (iw + g) * QP_STRIDE + kp + q;
            const int rb = (iw + g + 8) * QP_STRIDE + kp + q;
            uint32_t ah[4] = { Qh2[ra], Qh2[rb], Qh2[ra + 4], Qh2[rb + 4] };
            uint32_t al[4] = { Ql2[ra], Ql2[rb], Ql2[ra + 4], Ql2[rb + 4] };
            #pragma unroll
            for (int n = 0; n < 8; n++) {
                const int kb = (n * 8 + g) * QP_STRIDE + kp + q;
                uint32_t bh[2] = { Kh2[kb], Kh2[kb + 4] };
                uint32_t bl[2] = { Kl2[kb], Kl2[kb + 4] };
                mma16(ds[n], ah, bh);
                mma16(ds[n], ah, bl);
                mma16(ds[n], al, bh);
            }
        }

        #pragma unroll
        for (int n = 0; n < 8; n++) {
            float p0 = pexp30(ds[n][0]), p1 = pexp30(ds[n][1]);
            float p2 = pexp30(ds[n][2]), p3 = pexp30(ds[n][3]);
            ds[n][0] = p0; ds[n][1] = p1; ds[n][2] = p2; ds[n][3] = p3;
            ls0 += p0 + p1;
            ls1 += p2 + p3;
        }

        const int csel = q & 1;
        const int src1 = (lane & ~3) | (q >> 1);
        const int src2 = src1 + 2;
        #pragma unroll
        for (int jk = 0; jk < 8; jk++) {
            float t0 = __shfl_sync(0xffffffffu, ds[jk][0], src1);
            float t1 = __shfl_sync(0xffffffffu, ds[jk][1], src1);
            float t2 = __shfl_sync(0xffffffffu, ds[jk][2], src1);
            float t3 = __shfl_sync(0xffffffffu, ds[jk][3], src1);
            float u0 = __shfl_sync(0xffffffffu, ds[jk][0], src2);
            float u1 = __shfl_sync(0xffffffffu, ds[jk][1], src2);
            float u2 = __shfl_sync(0xffffffffu, ds[jk][2], src2);
            float u3 = __shfl_sync(0xffffffffu, ds[jk][3], src2);
            uint32_t pa[4] = { __float_as_uint(csel ? t1 : t0),
                               __float_as_uint(csel ? t3 : t2),
                               __float_as_uint(csel ? u1 : u0),
                               __float_as_uint(csel ? u3 : u2) };
            const int jb = jk * 8;
            #pragma unroll
            for (int nc = 0; nc < 16; nc++) {
                uint32_t vb[2] = { __float_as_uint(Vs[(nc * 8 + g) * QP_STRIDE + jb + q]),
                                   __float_as_uint(Vs[(nc * 8 + g) * QP_STRIDE + jb + q + 4]) };
                mma8(o[nc], pa, vb);
            }
        }
    }

    ls0 += __shfl_xor_sync(0xffffffffu, ls0, 1);
    ls0 += __shfl_xor_sync(0xffffffffu, ls0, 2);
    ls1 += __shfl_xor_sync(0xffffffffu, ls1, 1);
    ls1 += __shfl_xor_sync(0xffffffffu, ls1, 2);
    const float inv0 = 1.f / ls0, inv1 = 1.f / ls1;
    const int r0 = i0g + iw + g, r1 = r0 + 8;
    #pragma unroll
    for (int nc = 0; nc < 16; nc++) {
        const int cc = nc * 8 + 2 * q;
        *(float2*)&g_att[b][r0][cc] = make_float2(o[nc][0] * inv0, o[nc][1] * inv0);
        *(float2*)&g_att[b][r1][cc] = make_float2(o[nc][2] * inv1, o[nc][3] * inv1);
    }
}

// ============================================================================
// Kernel 3: W conv via bf16 3-term mma + bias + residual.  Block: [64 o x 64 n].
// ============================================================================
#define WATH 0
#define WATL 4352
#define WWH  8704
#define WWL  13056
#define WBS  17408
#define WCONV_SMEM_W (WBS + 64)      // 17472 u32 = 69888 B

__global__ __launch_bounds__(256) void wconv_mma_kernel(
    const float* __restrict__ x, const float* __restrict__ Wb,
    float* __restrict__ out)
{
    extern __shared__ uint32_t smu[];
    uint32_t* ath = smu + WATH;     // [64 n][68]
    uint32_t* atl = smu + WATL;
    uint32_t* wwh = smu + WWH;      // [64 o][68]
    uint32_t* wwl = smu + WWL;
    float*    bs  = (float*)(smu + WBS);

    const int b = blockIdx.z, og0 = blockIdx.y * 64, gn0 = blockIdx.x * 64;
    const int tid = threadIdx.x, wid = tid >> 5, lane = tid & 31;
    const int g = lane >> 2, q = lane & 3;
    if (tid < 64) bs[tid] = Wb[og0 + tid];

    // att tile: load [n][c] float4 (c-contiguous) and pack pairs directly
    const float* attb = &g_att[b][gn0][0];
    #pragma unroll
    for (int v = 0; v < 8; v++) {
        int id = tid + v * 256, n = id >> 5, c4 = (id & 31) * 4;
        float4 a = *(const float4*)&attb[(size_t)n * CI + c4];
        uint32_t h0 = bfp2(a.x, a.y), h1 = bfp2(a.z, a.w);
        uint32_t l0 = bfp2(a.x - blo(h0), a.y - bhi(h0));
        uint32_t l1 = bfp2(a.z - blo(h1), a.w - bhi(h1));
        const int p = c4 >> 1;
        *(uint2*)&ath[n * 68 + p] = make_uint2(h0, h1);
        *(uint2*)&atl[n * 68 + p] = make_uint2(l0, l1);
    }
    // ww tile: [64 o][64 pairs] hi/lo
    #pragma unroll
    for (int v = 0; v < 4; v++) {
        int id = tid + v * 256, o = id >> 4, p4 = (id & 15) * 4;
        *(uint4*)&wwh[o * 68 + p4] = *(const uint4*)&g_WWh[og0 + o][p4];
        *(uint4*)&wwl[o * 68 + p4] = *(const uint4*)&g_WWl[og0 + o][p4];
    }
    __syncthreads();

    const int mt = wid & 3, nh = wid >> 2, ar = mt * 16;
    float ds[4][4];
    #pragma unroll
    for (int n = 0; n < 4; n++)
        #pragma unroll
        for (int r = 0; r < 4; r++) ds[n][r] = 0.f;

    #pragma unroll
    for (int kc = 0; kc < 8; kc++) {
        const int kp = kc * 8;
        uint32_t ah[4] = { wwh[(ar + g) * 68 + kp + q], wwh[(ar + g + 8) * 68 + kp + q],
                           wwh[(ar + g) * 68 + kp + q + 4], wwh[(ar + g + 8) * 68 + kp + q + 4] };
        uint32_t al[4] = { wwl[(ar + g) * 68 + kp + q], wwl[(ar + g + 8) * 68 + kp + q],
                           wwl[(ar + g) * 68 + kp + q + 4], wwl[(ar + g + 8) * 68 + kp + q + 4] };
        #pragma unroll
        for (int nc = 0; nc < 4; nc++) {
            const int br = (nh * 32 + nc * 8 + g) * 68 + kp;
            uint32_t bh[2] = { ath[br + q], ath[br + q + 4] };
            uint32_t bl[2] = { atl[br + q], atl[br + q + 4] };
            mma16(ds[nc], ah, bh);
            mma16(ds[nc], ah, bl);
            mma16(ds[nc], al, bh);
        }
    }

    const int o0 = og0 + ar + g, o1 = o0 + 8;
    const float b0 = bs[ar + g], b1 = bs[ar + g + 8];
    #pragma unroll
    for (int nc = 0; nc < 4; nc++) {
        const int n = gn0 + nh * 32 + nc * 8 + 2 * q;
        size_t off0 = ((size_t)b * CIN + o0) * NPIX + n;
        size_t off1 = ((size_t)b * CIN + o1) * NPIX + n;
        float2 x0 = *(const float2*)&x[off0];
        float2 x1 = *(const float2*)&x[off1];
        *(float2*)&out[off0] = make_float2(ds[nc][0] + b0 + x0.x, ds[nc][1] + b0 + x0.y);
        *(float2*)&out[off1] = make_float2(ds[nc][2] + b1 + x1.x, ds[nc][3] + b1 + x1.y);
    }
}

// ============================================================================
extern "C" void kernel_launch(void* const* d_in, const int* in_sizes, int n_in,
                              void* d_out, int out_size)
{
    const float* x    = (const float*)d_in[0];
    const float* g_w  = (const float*)d_in[1];
    const float* g_b  = (const float*)d_in[2];
    const float* th_w = (const float*)d_in[3];
    const float* th_b = (const float*)d_in[4];
    const float* ph_w = (const float*)d_in[5];
    const float* ph_b = (const float*)d_in[6];
    const float* W_w  = (const float*)d_in[7];
    const float* W_b  = (const float*)d_in[8];
    float* out = (float*)d_out;

    prep_kernel<<<64, 256>>>(th_w, ph_w, g_w, W_w);

    const int proj_smem = PROJ_SMEM_W * 4;     // 73216 B
    cudaFuncSetAttribute(proj_mma_kernel,
                         cudaFuncAttributeMaxDynamicSharedMemorySize, proj_smem);
    proj_mma_kernel<<<dim3(64, 3, 8), 256, proj_smem>>>(x, th_b, ph_b, g_b);

    const int attn_smem = ATTN_SMEM_W * 4;     // 208896 B
    cudaFuncSetAttribute(attn_mma_kernel,
                         cudaFuncAttributeMaxDynamicSharedMemorySize, attn_smem);
    attn_mma_kernel<<<dim3(32, 8), 256, attn_smem>>>();

    const int wconv_smem = WCONV_SMEM_W * 4;   // 69888 B
    cudaFuncSetAttribute(wconv_mma_kernel,
                         cudaFuncAttributeMaxDynamicSharedMemorySize, wconv_smem);
    wconv_mma_kernel<<<dim3(64, 4, 8), 256, wconv_smem>>>(x, W_b, out);
}

// round 14
// speedup vs baseline: 1.1835x; 1.0020x over previous
#include <cuda_runtime.h>
#include <cstdint>

#define CIN  256
#define CI   128
#define NPIX 4096
#define BATCH 8

// Scratch. theta/phi PRE-SPLIT packed bf16x2 hi/lo [n][64 pairs]; g tf32 [c][n];
// att n-major. Weights pre-split by prep_kernel.
__device__ uint32_t g_qh[BATCH][NPIX][64];
__device__ uint32_t g_ql[BATCH][NPIX][64];
__device__ uint32_t g_kh[BATCH][NPIX][64];
__device__ uint32_t g_kl[BATCH][NPIX][64];
__device__ float    g_v [BATCH][CI][NPIX];
__device__ float    g_att[BATCH][NPIX][CI];
__device__ uint32_t g_wh[3][CI][128];     // proj weights, pairs over cin
__device__ uint32_t g_wl[3][CI][128];
__device__ uint32_t g_WWh[CIN][64];       // W conv weights, pairs over ci
__device__ uint32_t g_WWl[CIN][64];

// ---- mma.sync helpers ----
__device__ __forceinline__ uint32_t tf32r(float f) {
    uint32_t u; asm("cvt.rna.tf32.f32 %0,%1;" : "=r"(u) : "f"(f)); return u;
}
__device__ __forceinline__ void mma8(float* d, const uint32_t* a, const uint32_t* b) {
    asm volatile("mma.sync.aligned.m16n8k8.row.col.f32.tf32.tf32.f32 "
        "{%0,%1,%2,%3}, {%4,%5,%6,%7}, {%8,%9}, {%0,%1,%2,%3};"
        : "+f"(d[0]), "+f"(d[1]), "+f"(d[2]), "+f"(d[3])
        : "r"(a[0]), "r"(a[1]), "r"(a[2]), "r"(a[3]), "r"(b[0]), "r"(b[1]));
}
__device__ __forceinline__ void mma16(float* d, const uint32_t* a, const uint32_t* b) {
    asm volatile("mma.sync.aligned.m16n8k16.row.col.f32.bf16.bf16.f32 "
        "{%0,%1,%2,%3}, {%4,%5,%6,%7}, {%8,%9}, {%0,%1,%2,%3};"
        : "+f"(d[0]), "+f"(d[1]), "+f"(d[2]), "+f"(d[3])
        : "r"(a[0]), "r"(a[1]), "r"(a[2]), "r"(a[3]), "r"(b[0]), "r"(b[1]));
}
// pack two floats to bf16x2 {lo half = x, hi half = y}
__device__ __forceinline__ uint32_t bfp2(float x, float y) {
    uint32_t r; asm("cvt.rn.bf16x2.f32 %0,%1,%2;" : "=r"(r) : "f"(y), "f"(x)); return r;
}
__device__ __forceinline__ float blo(uint32_t h) { return __uint_as_float(h << 16); }
__device__ __forceinline__ float bhi(uint32_t h) { return __uint_as_float(h & 0xFFFF0000u); }
// cp.async 16B
__device__ __forceinline__ void cpa16(uint32_t saddr, const void* gaddr) {
    asm volatile("cp.async.cg.shared.global [%0],[%1],16;" :: "r"(saddr), "l"(gaddr));
}
#define CP_COMMIT() asm volatile("cp.async.commit_group;" ::: "memory")
#define CP_WAIT0()  asm volatile("cp.async.wait_group 0;" ::: "memory")

// fast exp(s-30) on FMA pipe, tf32-truncated
__device__ __forceinline__ float pexp30(float s) {
    float y = fmaf(s, 1.44269504f, -43.28085123f);
    int ei = __float2int_rn(y);
    float f = y - (float)ei;
    float pl = fmaf(f, 1.3333558e-3f, 9.6181291e-3f);
    pl = fmaf(f, pl, 5.5504109e-2f);
    pl = fmaf(f, pl, 2.4022651e-1f);
    pl = fmaf(f, pl, 6.9314718e-1f);
    pl = fmaf(f, pl, 1.0f);
    int e2 = ei + 127;
    e2 = e2 < 0 ? 0 : (e2 > 254 ? 254 : e2);
    float p = pl * __int_as_float(e2 << 23);
    return __uint_as_float(tf32r(p));
}

// ============================================================================
// Kernel 0: weight prep — split all weights into packed bf16x2 hi/lo once.
// ============================================================================
__global__ __launch_bounds__(256) void prep_kernel(
    const float* __restrict__ tw, const float* __restrict__ pw,
    const float* __restrict__ gw, const float* __restrict__ Ww)
{
    const int gid = blockIdx.x * 256 + threadIdx.x;
    const float* ws[3] = { tw, pw, gw };
    const int co = gid >> 7, pr = gid & 127;
    #pragma unroll
    for (int pj = 0; pj < 3; pj++) {
        float a = ws[pj][co * CIN + 2 * pr], c = ws[pj][co * CIN + 2 * pr + 1];
        uint32_t h = bfp2(a, c);
        g_wh[pj][co][pr] = h;
        g_wl[pj][co][pr] = bfp2(a - blo(h), c - bhi(h));
    }
    {
        const int o = gid >> 6, p2 = gid & 63;
        float a = Ww[o * CI + 2 * p2], c = Ww[o * CI + 2 * p2 + 1];
        uint32_t h = bfp2(a, c);
        g_WWh[o][p2] = h;
        g_WWl[o][p2] = bfp2(a - blo(h), c - bhi(h));
    }
}

// ============================================================================
// Kernel 1: proj via bf16 3-TERM mma (R11 exact).  Block: [128 co x 64 n].
// ============================================================================
#define PXR   0                       // x raw chunk [64 c][68] f32
#define PXPH  4352                    // x packed hi [64 n][36]
#define PXPL  (PXPH + 2304)
#define PWH   (PXPL + 2304)           // w packed hi [128 co][36]
#define PWL   (PWH + 4608)
#define PBS   (PWL + 4608)            // bias 128 f32
#define PROJ_SMEM_W (PBS + 128)       // 18304 u32 = 73216 B

__global__ __launch_bounds__(256) void proj_mma_kernel(
    const float* __restrict__ x,
    const float* __restrict__ tb, const float* __restrict__ pb,
    const float* __restrict__ gb)
{
    extern __shared__ uint32_t smu[];
    float*    xr  = (float*)(smu + PXR);
    uint32_t* xph = smu + PXPH;
    uint32_t* xpl = smu + PXPL;
    uint32_t* wh  = smu + PWH;
    uint32_t* wl  = smu + PWL;
    float*    bs  = (float*)(smu + PBS);

    const int b = blockIdx.z, pj = blockIdx.y, n0g = blockIdx.x * 64;
    const int tid = threadIdx.x, wid = tid >> 5, lane = tid & 31;
    const int g = lane >> 2, q = lane & 3;
    const float* bias = (pj == 0) ? tb : (pj == 1) ? pb : gb;
    if (tid < 128) bs[tid] = bias[tid];

    const float* xb = x + (size_t)b * CIN * NPIX;
    const uint32_t* wsh = &g_wh[pj][0][0];
    const uint32_t* wsl = &g_wl[pj][0][0];

    float ds[8][4];
    #pragma unroll
    for (int n = 0; n < 8; n++)
        #pragma unroll
        for (int r = 0; r < 4; r++) ds[n][r] = 0.f;

    for (int ck = 0; ck < 4; ck++) {
        const int c0 = ck * 64;
        __syncthreads();
        // x chunk [64 c][64 n] raw
        #pragma unroll
        for (int v = 0; v < 4; v++) {
            int id = tid + v * 256, cc = id >> 4, n4 = (id & 15) * 4;
            *(float4*)&xr[cc * 68 + n4] =
                *(const float4*)&xb[(size_t)(c0 + cc) * NPIX + n0g + n4];
        }
        // w chunk [128 co][32 pairs] hi/lo
        #pragma unroll
        for (int v = 0; v < 4; v++) {
            int id = tid + v * 256, co = id >> 3, p4 = (id & 7) * 4;
            *(uint4*)&wh[co * 36 + p4] = *(const uint4*)&wsh[co * 128 + ck * 32 + p4];
            *(uint4*)&wl[co * 36 + p4] = *(const uint4*)&wsl[co * 128 + ck * 32 + p4];
        }
        __syncthreads();
        // pack x: transpose to [n][pair] bf16 hi/lo
        #pragma unroll
        for (int v = 0; v < 8; v++) {
            int id = tid + v * 256, n = id & 63, pc = id >> 6;   // pc 0..31
            float a = xr[(2 * pc) * 68 + n], c = xr[(2 * pc + 1) * 68 + n];
            uint32_t h = bfp2(a, c);
            xph[n * 36 + pc] = h;
            xpl[n * 36 + pc] = bfp2(a - blo(h), c - bhi(h));
        }
        __syncthreads();

        if (pj <= 1) {
            const int mt = wid & 3, ch = wid >> 2, ar = mt * 16;
            #pragma unroll
            for (int kc = 0; kc < 4; kc++) {
                const int kp = kc * 8;
                uint32_t ah[4] = { xph[(ar + g) * 36 + kp + q], xph[(ar + g + 8) * 36 + kp + q],
                                   xph[(ar + g) * 36 + kp + q + 4], xph[(ar + g + 8) * 36 + kp + q + 4] };
                uint32_t al[4] = { xpl[(ar + g) * 36 + kp + q], xpl[(ar + g + 8) * 36 + kp + q],
                                   xpl[(ar + g) * 36 + kp + q + 4], xpl[(ar + g + 8) * 36 + kp + q + 4] };
                #pragma unroll
                for (int nc = 0; nc < 8; nc++) {
                    const int br = (ch * 64 + nc * 8 + g) * 36 + kp;
                    uint32_t bh[2] = { wh[br + q], wh[br + q + 4] };
                    uint32_t bl[2] = { wl[br + q], wl[br + q + 4] };
                    mma16(ds[nc], ah, bh);
                    mma16(ds[nc], ah, bl);
                    mma16(ds[nc], al, bh);
                }
            }
        } else {
            const int ar = wid * 16;
            #pragma unroll
            for (int kc = 0; kc < 4; kc++) {
                const int kp = kc * 8;
                uint32_t ah[4] = { wh[(ar + g) * 36 + kp + q], wh[(ar + g + 8) * 36 + kp + q],
                                   wh[(ar + g) * 36 + kp + q + 4], wh[(ar + g + 8) * 36 + kp + q + 4] };
                uint32_t al[4] = { wl[(ar + g) * 36 + kp + q], wl[(ar + g + 8) * 36 + kp + q],
                                   wl[(ar + g) * 36 + kp + q + 4], wl[(ar + g + 8) * 36 + kp + q + 4] };
                #pragma unroll
                for (int nc = 0; nc < 8; nc++) {
                    const int br = (nc * 8 + g) * 36 + kp;
                    uint32_t bh[2] = { xph[br + q], xph[br + q + 4] };
                    uint32_t bl[2] = { xpl[br + q], xpl[br + q + 4] };
                    mma16(ds[nc], ah, bh);
                    mma16(ds[nc], ah, bl);
                    mma16(ds[nc], al, bh);
                }
            }
        }
    }

    if (pj <= 1) {
        uint32_t* ph = (pj == 0) ? &g_qh[b][0][0] : &g_kh[b][0][0];
        uint32_t* pl = (pj == 0) ? &g_ql[b][0][0] : &g_kl[b][0][0];
        const int mt = wid & 3, ch = wid >> 2;
        const int nr0 = n0g + mt * 16 + g, nr1 = nr0 + 8;
        #pragma unroll
        for (int nc = 0; nc < 8; nc++) {
            const int co0 = ch * 64 + nc * 8 + 2 * q;
            const float b0 = bs[co0], b1 = bs[co0 + 1];
            float v0 = ds[nc][0] + b0, v1 = ds[nc][1] + b1;
            float v2 = ds[nc][2] + b0, v3 = ds[nc][3] + b1;
            uint32_t h0 = bfp2(v0, v1), h1 = bfp2(v2, v3);
            uint32_t l0 = bfp2(v0 - blo(h0), v1 - bhi(h0));
            uint32_t l1 = bfp2(v2 - blo(h1), v3 - bhi(h1));
            const int pr = ch * 32 + nc * 4 + q;
            ph[(size_t)nr0 * 64 + pr] = h0;  pl[(size_t)nr0 * 64 + pr] = l0;
            ph[(size_t)nr1 * 64 + pr] = h1;  pl[(size_t)nr1 * 64 + pr] = l1;
        }
    } else {
        float* outp = &g_v[b][0][0];
        const int c0 = wid * 16 + g, c1 = c0 + 8;
        const float b0 = bs[c0], b1 = bs[c1];
        #pragma unroll
        for (int nc = 0; nc < 8; nc++) {
            const int n = n0g + nc * 8 + 2 * q;
            *(float2*)&outp[(size_t)c0 * NPIX + n] = make_float2(
                __uint_as_float(tf32r(ds[nc][0] + b0)), __uint_as_float(tf32r(ds[nc][1] + b0)));
            *(float2*)&outp[(size_t)c1 * NPIX + n] = make_float2(
                __uint_as_float(tf32r(ds[nc][2] + b1)), __uint_as_float(tf32r(ds[nc][3] + b1)));
        }
    }
}

// ============================================================================
// Kernel 2: attention (unchanged — tensor-pipe-bound at floor).
// ============================================================================
#define QP_STRIDE 68
#define SM_QH 0
#define SM_QL (128 * QP_STRIDE)
#define SM_ST (2 * 128 * QP_STRIDE)
#define STG   (2 * 64 * QP_STRIDE + 128 * QP_STRIDE)
#define ATTN_SMEM_W (SM_ST + 2 * STG)            // 52224 u32 = 208896 B

__global__ __launch_bounds__(256, 1) void attn_mma_kernel()
{
    extern __shared__ uint32_t smw[];
    uint32_t* Qh2 = smw + SM_QH;
    uint32_t* Ql2 = smw + SM_QL;
    const uint32_t smb = (uint32_t)__cvta_generic_to_shared(smw);

    const int tid = threadIdx.x, wid = tid >> 5, lane = tid & 31;
    const int g = lane >> 2, q = lane & 3;
    const int b = blockIdx.y, i0g = blockIdx.x * 128;
    const int iw = wid * 16;

    {
        const uint32_t base = smb + 4u * SM_ST;
        const uint32_t* sKh = &g_kh[b][0][0];
        const uint32_t* sKl = &g_kl[b][0][0];
        const float*    sV  = &g_v[b][0][0];
        #pragma unroll
        for (int v = 0; v < 4; v++) {
            int id = tid + v * 256, j = id >> 4, ch = (id & 15) * 4;
            cpa16(base + 4u * (j * QP_STRIDE + ch), sKh + j * 64 + ch);
        }
        #pragma unroll
        for (int v = 0; v < 4; v++) {
            int id = tid + v * 256, j = id >> 4, ch = (id & 15) * 4;
            cpa16(base + 4u * (64 * QP_STRIDE + j * QP_STRIDE + ch), sKl + j * 64 + ch);
        }
        #pragma unroll
        for (int v = 0; v < 8; v++) {
            int id = tid + v * 256, c = id >> 4, ch = (id & 15) * 4;
            cpa16(base + 4u * (128 * QP_STRIDE + c * QP_STRIDE + ch), sV + (size_t)c * NPIX + ch);
        }
        CP_COMMIT();
    }
    {
        const uint32_t* sQh = &g_qh[b][i0g][0];
        const uint32_t* sQl = &g_ql[b][i0g][0];
        #pragma unroll
        for (int v = 0; v < 8; v++) {
            int id = tid + v * 256, i = id >> 4, ch = (id & 15) * 4;
            *(uint4*)&Qh2[i * QP_STRIDE + ch] = *(const uint4*)&sQh[i * 64 + ch];
            *(uint4*)&Ql2[i * QP_STRIDE + ch] = *(const uint4*)&sQl[i * 64 + ch];
        }
    }

    float o[16][4];
    #pragma unroll
    for (int n = 0; n < 16; n++)
        #pragma unroll
        for (int r = 0; r < 4; r++) o[n][r] = 0.f;
    float ls0 = 0.f, ls1 = 0.f;

    for (int t = 0; t < 64; t++) {
        const int s = t & 1;
        CP_WAIT0();
        __syncthreads();

        if (t < 63) {
            const int j1 = (t + 1) * 64;
            const uint32_t base = smb + 4u * (SM_ST + (s ^ 1) * STG);
            const uint32_t* sKh = &g_kh[b][j1][0];
            const uint32_t* sKl = &g_kl[b][j1][0];
            const float*    sV  = &g_v[b][0][j1];
            #pragma unroll
            for (int v = 0; v < 4; v++) {
                int id = tid + v * 256, j = id >> 4, ch = (id & 15) * 4;
                cpa16(base + 4u * (j * QP_STRIDE + ch), sKh + j * 64 + ch);
            }
            #pragma unroll
            for (int v = 0; v < 4; v++) {
                int id = tid + v * 256, j = id >> 4, ch = (id & 15) * 4;
                cpa16(base + 4u * (64 * QP_STRIDE + j * QP_STRIDE + ch), sKl + j * 64 + ch);
            }
            #pragma unroll
            for (int v = 0; v < 8; v++) {
                int id = tid + v * 256, c = id >> 4, ch = (id & 15) * 4;
                cpa16(base + 4u * (128 * QP_STRIDE + c * QP_STRIDE + ch), sV + (size_t)c * NPIX + ch);
            }
            CP_COMMIT();
        }

        uint32_t* Kh2 = smw + SM_ST + s * STG;
        uint32_t* Kl2 = Kh2 + 64 * QP_STRIDE;
        float*    Vs  = (float*)(Kh2 + 128 * QP_STRIDE);

        float ds[8][4];
        #pragma unroll
        for (int n = 0; n < 8; n++)
            #pragma unroll
            for (int r = 0; r < 4; r++) ds[n][r] = 0.f;

        #pragma unroll
        for (int kc = 0; kc < 8; kc++) {
            const int kp = kc * 8;
            const int ra = (iw + g) * QP_STRIDE + kp + q;
            const int rb = (iw + g + 8) * QP_STRIDE + kp + q;
            uint32_t ah[4] = { Qh2[ra], Qh2[rb], Qh2[ra + 4], Qh2[rb + 4] };
            uint32_t al[4] = { Ql2[ra], Ql2[rb], Ql2[ra + 4], Ql2[rb + 4] };
            #pragma unroll
            for (int n = 0; n < 8; n++) {
                const int kb = (n * 8 + g) * QP_STRIDE + kp + q;
                uint32_t bh[2] = { Kh2[kb], Kh2[kb + 4] };
                uint32_t bl[2] = { Kl2[kb], Kl2[kb + 4] };
                mma16(ds[n], ah, bh);
                mma16(ds[n], ah, bl);
                mma16(ds[n], al, bh);
            }
        }

        #pragma unroll
        for (int n = 0; n < 8; n++) {
            float p0 = pexp30(ds[n][0]), p1 = pexp30(ds[n][1]);
            float p2 = pexp30(ds[n][2]), p3 = pexp30(ds[n][3]);
            ds[n][0] = p0; ds[n][1] = p1; ds[n][2] = p2; ds[n][3] = p3;
            ls0 += p0 + p1;
            ls1 += p2 + p3;
        }

        const int csel = q & 1;
        const int src1 = (lane & ~3) | (q >> 1);
        const int src2 = src1 + 2;
        #pragma unroll
        for (int jk = 0; jk < 8; jk++) {
            float t0 = __shfl_sync(0xffffffffu, ds[jk][0], src1);
            float t1 = __shfl_sync(0xffffffffu, ds[jk][1], src1);
            float t2 = __shfl_sync(0xffffffffu, ds[jk][2], src1);
            float t3 = __shfl_sync(0xffffffffu, ds[jk][3], src1);
            float u0 = __shfl_sync(0xffffffffu, ds[jk][0], src2);
            float u1 = __shfl_sync(0xffffffffu, ds[jk][1], src2);
            float u2 = __shfl_sync(0xffffffffu, ds[jk][2], src2);
            float u3 = __shfl_sync(0xffffffffu, ds[jk][3], src2);
            uint32_t pa[4] = { __float_as_uint(csel ? t1 : t0),
                               __float_as_uint(csel ? t3 : t2),
                               __float_as_uint(csel ? u1 : u0),
                               __float_as_uint(csel ? u3 : u2) };
            const int jb = jk * 8;
            #pragma unroll
            for (int nc = 0; nc < 16; nc++) {
                uint32_t vb[2] = { __float_as_uint(Vs[(nc * 8 + g) * QP_STRIDE + jb + q]),
                                   __float_as_uint(Vs[(nc * 8 + g) * QP_STRIDE + jb + q + 4]) };
                mma8(o[nc], pa, vb);
            }
        }
    }

    ls0 += __shfl_xor_sync(0xffffffffu, ls0, 1);
    ls0 += __shfl_xor_sync(0xffffffffu, ls0, 2);
    ls1 += __shfl_xor_sync(0xffffffffu, ls1, 1);
    ls1 += __shfl_xor_sync(0xffffffffu, ls1, 2);
    const float inv0 = 1.f / ls0, inv1 = 1.f / ls1;
    const int r0 = i0g + iw + g, r1 = r0 + 8;
    #pragma unroll
    for (int nc = 0; nc < 16; nc++) {
        const int cc = nc * 8 + 2 * q;
        *(float2*)&g_att[b][r0][cc] = make_float2(o[nc][0] * inv0, o[nc][1] * inv0);
        *(float2*)&g_att[b][r1][cc] = make_float2(o[nc][2] * inv1, o[nc][3] * inv1);
    }
}

// ============================================================================
// Kernel 3: W conv, tiles [64 o x 128 n], 3-term, 2 CTAs/SM.
// ============================================================================
#define WATH 0                           // att hi [128 n][68]
#define WATL 8704
#define WWH  17408                       // W hi [64 o][68]
#define WWL  21760
#define WBS  26112
#define WCONV_SMEM_W (WBS + 64)          // 26176 u32 = 104704 B

__global__ __launch_bounds__(256, 2) void wconv_mma_kernel(
    const float* __restrict__ x, const float* __restrict__ Wb,
    float* __restrict__ out)
{
    extern __shared__ uint32_t smu[];
    uint32_t* ath = smu + WATH;
    uint32_t* atl = smu + WATL;
    uint32_t* wwh = smu + WWH;
    uint32_t* wwl = smu + WWL;
    float*    bs  = (float*)(smu + WBS);

    const int b = blockIdx.z, og0 = blockIdx.y * 64, gn0 = blockIdx.x * 128;
    const int tid = threadIdx.x, wid = tid >> 5, lane = tid & 31;
    const int g = lane >> 2, q = lane & 3;
    if (tid < 64) bs[tid] = Wb[og0 + tid];

    const float* attb = &g_att[b][gn0][0];
    #pragma unroll
    for (int v = 0; v < 16; v++) {
        int id = tid + v * 256, n = id >> 5, c4 = (id & 31) * 4;
        float4 a = *(const float4*)&attb[(size_t)n * CI + c4];
        uint32_t h0 = bfp2(a.x, a.y), h1 = bfp2(a.z, a.w);
        uint32_t l0 = bfp2(a.x - blo(h0), a.y - bhi(h0));
        uint32_t l1 = bfp2(a.z - blo(h1), a.w - bhi(h1));
        const int p = c4 >> 1;
        *(uint2*)&ath[n * 68 + p] = make_uint2(h0, h1);
        *(uint2*)&atl[n * 68 + p] = make_uint2(l0, l1);
    }
    #pragma unroll
    for (int v = 0; v < 4; v++) {
        int id = tid + v * 256, o = id >> 4, p4 = (id & 15) * 4;
        *(uint4*)&wwh[o * 68 + p4] = *(const uint4*)&g_WWh[og0 + o][p4];
        *(uint4*)&wwl[o * 68 + p4] = *(const uint4*)&g_WWl[og0 + o][p4];
    }
    __syncthreads();

    const int mt = wid & 3, nh = wid >> 2, ar = mt * 16;
    float ds[8][4];
    #pragma unroll
    for (int n = 0; n < 8; n++)
        #pragma unroll
        for (int r = 0; r < 4; r++) ds[n][r] = 0.f;

    #pragma unroll
    for (int kc = 0; kc < 8; kc++) {
        const int kp = kc * 8;
        uint32_t ah[4] = { wwh[(ar + g) * 68 + kp + q], wwh[(ar + g + 8) * 68 + kp + q],
                           wwh[(ar + g) * 68 + kp + q + 4], wwh[(ar + g + 8) * 68 + kp + q + 4] };
        uint32_t al[4] = { wwl[(ar + g) * 68 + kp + q], wwl[(ar + g + 8) * 68 + kp + q],
                           wwl[(ar + g) * 68 + kp + q + 4], wwl[(ar + g + 8) * 68 + kp + q + 4] };
        #pragma unroll
        for (int nc = 0; nc < 8; nc++) {
            const int br = (nh * 64 + nc * 8 + g) * 68 + kp;
            uint32_t bh[2] = { ath[br + q], ath[br + q + 4] };
            uint32_t bl[2] = { atl[br + q], atl[br + q + 4] };
            mma16(ds[nc], ah, bh);
            mma16(ds[nc], ah, bl);
            mma16(ds[nc], al, bh);
        }
    }

    const int o0 = og0 + ar + g, o1 = o0 + 8;
    const float b0 = bs[ar + g], b1 = bs[ar + g + 8];
    #pragma unroll
    for (int nc = 0; nc < 8; nc++) {
        const int n = gn0 + nh * 64 + nc * 8 + 2 * q;
        size_t off0 = ((size_t)b * CIN + o0) * NPIX + n;
        size_t off1 = ((size_t)b * CIN + o1) * NPIX + n;
        float2 x0 = *(const float2*)&x[off0];
        float2 x1 = *(const float2*)&x[off1];
        *(float2*)&out[off0] = make_float2(ds[nc][0] + b0 + x0.x, ds[nc][1] + b0 + x0.y);
        *(float2*)&out[off1] = make_float2(ds[nc][2] + b1 + x1.x, ds[nc][3] + b1 + x1.y);
    }
}

// ============================================================================
extern "C" void kernel_launch(void* const* d_in, const int* in_sizes, int n_in,
                              void* d_out, int out_size)
{
    const float* x    = (const float*)d_in[0];
    const float* g_w  = (const float*)d_in[1];
    const float* g_b  = (const float*)d_in[2];
    const float* th_w = (const float*)d_in[3];
    const float* th_b = (const float*)d_in[4];
    const float* ph_w = (const float*)d_in[5];
    const float* ph_b = (const float*)d_in[6];
    const float* W_w  = (const float*)d_in[7];
    const float* W_b  = (const float*)d_in[8];
    float* out = (float*)d_out;

    prep_kernel<<<64, 256>>>(th_w, ph_w, g_w, W_w);

    const int proj_smem = PROJ_SMEM_W * 4;     // 73216 B
    cudaFuncSetAttribute(proj_mma_kernel,
                         cudaFuncAttributeMaxDynamicSharedMemorySize, proj_smem);
    proj_mma_kernel<<<dim3(64, 3, 8), 256, proj_smem>>>(x, th_b, ph_b, g_b);

    const int attn_smem = ATTN_SMEM_W * 4;     // 208896 B
    cudaFuncSetAttribute(attn_mma_kernel,
                         cudaFuncAttributeMaxDynamicSharedMemorySize, attn_smem);
    attn_mma_kernel<<<dim3(32, 8), 256, attn_smem>>>();

    const int wconv_smem = WCONV_SMEM_W * 4;   // 104704 B
    cudaFuncSetAttribute(wconv_mma_kernel,
                         cudaFuncAttributeMaxDynamicSharedMemorySize, wconv_smem);
    wconv_mma_kernel<<<dim3(32, 4, 8), 256, wconv_smem>>>(x, W_b, out);
}

// round 17
// speedup vs baseline: 1.1877x; 1.0035x over previous
#include <cuda_runtime.h>
#include <cstdint>

#define CIN  256
#define CI   128
#define NPIX 4096
#define BATCH 8

// Scratch. theta/phi PRE-SPLIT packed bf16x2 hi/lo [n][64 pairs]; g tf32 [c][n];
// att n-major. Weights and x pre-split by prep kernels.
__device__ uint32_t g_qh[BATCH][NPIX][64];
__device__ uint32_t g_ql[BATCH][NPIX][64];
__device__ uint32_t g_kh[BATCH][NPIX][64];
__device__ uint32_t g_kl[BATCH][NPIX][64];
__device__ float    g_v [BATCH][CI][NPIX];
__device__ float    g_att[BATCH][NPIX][CI];
__device__ uint32_t g_wh[3][CI][128];     // proj weights, pairs over cin
__device__ uint32_t g_wl[3][CI][128];
__device__ uint32_t g_WWh[CIN][64];       // W conv weights, pairs over ci
__device__ uint32_t g_WWl[CIN][64];
__device__ uint32_t g_xh[BATCH][NPIX][128];  // x packed [n][pair-over-c] hi
__device__ uint32_t g_xl[BATCH][NPIX][128];  // lo

// ---- mma.sync helpers ----
__device__ __forceinline__ uint32_t tf32r(float f) {
    uint32_t u; asm("cvt.rna.tf32.f32 %0,%1;" : "=r"(u) : "f"(f)); return u;
}
__device__ __forceinline__ void mma8(float* d, const uint32_t* a, const uint32_t* b) {
    asm volatile("mma.sync.aligned.m16n8k8.row.col.f32.tf32.tf32.f32 "
        "{%0,%1,%2,%3}, {%4,%5,%6,%7}, {%8,%9}, {%0,%1,%2,%3};"
        : "+f"(d[0]), "+f"(d[1]), "+f"(d[2]), "+f"(d[3])
        : "r"(a[0]), "r"(a[1]), "r"(a[2]), "r"(a[3]), "r"(b[0]), "r"(b[1]));
}
__device__ __forceinline__ void mma16(float* d, const uint32_t* a, const uint32_t* b) {
    asm volatile("mma.sync.aligned.m16n8k16.row.col.f32.bf16.bf16.f32 "
        "{%0,%1,%2,%3}, {%4,%5,%6,%7}, {%8,%9}, {%0,%1,%2,%3};"
        : "+f"(d[0]), "+f"(d[1]), "+f"(d[2]), "+f"(d[3])
        : "r"(a[0]), "r"(a[1]), "r"(a[2]), "r"(a[3]), "r"(b[0]), "r"(b[1]));
}
// pack two floats to bf16x2 {lo half = x, hi half = y}
__device__ __forceinline__ uint32_t bfp2(float x, float y) {
    uint32_t r; asm("cvt.rn.bf16x2.f32 %0,%1,%2;" : "=r"(r) : "f"(y), "f"(x)); return r;
}
__device__ __forceinline__ float blo(uint32_t h) { return __uint_as_float(h << 16); }
__device__ __forceinline__ float bhi(uint32_t h) { return __uint_as_float(h & 0xFFFF0000u); }
// cp.async 16B
__device__ __forceinline__ void cpa16(uint32_t saddr, const void* gaddr) {
    asm volatile("cp.async.cg.shared.global [%0],[%1],16;" :: "r"(saddr), "l"(gaddr));
}
#define CP_COMMIT() asm volatile("cp.async.commit_group;" ::: "memory")
#define CP_WAIT0()  asm volatile("cp.async.wait_group 0;" ::: "memory")

// fast exp(s-30) on FMA pipe, tf32-truncated
__device__ __forceinline__ float pexp30(float s) {
    float y = fmaf(s, 1.44269504f, -43.28085123f);
    int ei = __float2int_rn(y);
    float f = y - (float)ei;
    float pl = fmaf(f, 1.3333558e-3f, 9.6181291e-3f);
    pl = fmaf(f, pl, 5.5504109e-2f);
    pl = fmaf(f, pl, 2.4022651e-1f);
    pl = fmaf(f, pl, 6.9314718e-1f);
    pl = fmaf(f, pl, 1.0f);
    int e2 = ei + 127;
    e2 = e2 < 0 ? 0 : (e2 > 254 ? 254 : e2);
    float p = pl * __int_as_float(e2 << 23);
    return __uint_as_float(tf32r(p));
}

// ============================================================================
// Kernel 0a: weight prep — split all weights into packed bf16x2 hi/lo once.
// ============================================================================
__global__ __launch_bounds__(256) void prep_kernel(
    const float* __restrict__ tw, const float* __restrict__ pw,
    const float* __restrict__ gw, const float* __restrict__ Ww)
{
    const int gid = blockIdx.x * 256 + threadIdx.x;
    const float* ws[3] = { tw, pw, gw };
    const int co = gid >> 7, pr = gid & 127;
    #pragma unroll
    for (int pj = 0; pj < 3; pj++) {
        float a = ws[pj][co * CIN + 2 * pr], c = ws[pj][co * CIN + 2 * pr + 1];
        uint32_t h = bfp2(a, c);
        g_wh[pj][co][pr] = h;
        g_wl[pj][co][pr] = bfp2(a - blo(h), c - bhi(h));
    }
    {
        const int o = gid >> 6, p2 = gid & 63;
        float a = Ww[o * CI + 2 * p2], c = Ww[o * CI + 2 * p2 + 1];
        uint32_t h = bfp2(a, c);
        g_WWh[o][p2] = h;
        g_WWl[o][p2] = bfp2(a - blo(h), c - bhi(h));
    }
}

// ============================================================================
// Kernel 0b: x prep — transpose+split x into packed bf16x2 hi/lo [n][pair].
// ============================================================================
__global__ __launch_bounds__(256) void prep2_kernel(const float* __restrict__ x)
{
    __shared__ float xr[64 * 68];
    const int b = blockIdx.y, n0g = blockIdx.x * 64;
    const int tid = threadIdx.x;
    const float* xb = x + (size_t)b * CIN * NPIX;

    for (int ck = 0; ck < 4; ck++) {
        __syncthreads();
        #pragma unroll
        for (int v = 0; v < 4; v++) {
            int id = tid + v * 256, cc = id >> 4, n4 = (id & 15) * 4;
            *(float4*)&xr[cc * 68 + n4] =
                *(const float4*)&xb[(size_t)(ck * 64 + cc) * NPIX + n0g + n4];
        }
        __syncthreads();
        #pragma unroll
        for (int v = 0; v < 8; v++) {
            int id = tid + v * 256, pc = id & 31, n = id >> 5;
            float a = xr[(2 * pc) * 68 + n], c = xr[(2 * pc + 1) * 68 + n];
            uint32_t h = bfp2(a, c);
            g_xh[b][n0g + n][ck * 32 + pc] = h;
            g_xl[b][n0g + n][ck * 32 + pc] = bfp2(a - blo(h), c - bhi(h));
        }
    }
}

// ============================================================================
// Kernel 1: proj via bf16 3-TERM mma, pre-packed x.  Block: [128 co x 64 n].
// ============================================================================
#define PXPH  0                       // x packed hi [64 n][36]
#define PXPL  2304
#define PWH   4608                    // w packed hi [128 co][36]
#define PWL   9216
#define PBS   13824                   // bias 128 f32
#define PROJ_SMEM_W (PBS + 128)       // 13952 u32 = 55808 B

__global__ __launch_bounds__(256) void proj_mma_kernel(
    const float* __restrict__ tb, const float* __restrict__ pb,
    const float* __restrict__ gb)
{
    extern __shared__ uint32_t smu[];
    uint32_t* xph = smu + PXPH;
    uint32_t* xpl = smu + PXPL;
    uint32_t* wh  = smu + PWH;
    uint32_t* wl  = smu + PWL;
    float*    bs  = (float*)(smu + PBS);
    const uint32_t smb = (uint32_t)__cvta_generic_to_shared(smu);

    const int b = blockIdx.z, pj = blockIdx.y, n0g = blockIdx.x * 64;
    const int tid = threadIdx.x, wid = tid >> 5, lane = tid & 31;
    const int g = lane >> 2, q = lane & 3;
    const float* bias = (pj == 0) ? tb : (pj == 1) ? pb : gb;
    if (tid < 128) bs[tid] = bias[tid];

    const uint32_t* wsh = &g_wh[pj][0][0];
    const uint32_t* wsl = &g_wl[pj][0][0];

    float ds[8][4];
    #pragma unroll
    for (int n = 0; n < 8; n++)
        #pragma unroll
        for (int r = 0; r < 4; r++) ds[n][r] = 0.f;

    for (int ck = 0; ck < 4; ck++) {
        __syncthreads();
        #pragma unroll
        for (int v = 0; v < 2; v++) {
            int id = tid + v * 256, n = id >> 3, p4 = (id & 7) * 4;
            cpa16(smb + 4u * (PXPH + n * 36 + p4), &g_xh[b][n0g + n][ck * 32 + p4]);
            cpa16(smb + 4u * (PXPL + n * 36 + p4), &g_xl[b][n0g + n][ck * 32 + p4]);
        }
        #pragma unroll
        for (int v = 0; v < 4; v++) {
            int id = tid + v * 256, co = id >> 3, p4 = (id & 7) * 4;
            cpa16(smb + 4u * (PWH + co * 36 + p4), wsh + co * 128 + ck * 32 + p4);
            cpa16(smb + 4u * (PWL + co * 36 + p4), wsl + co * 128 + ck * 32 + p4);
        }
        CP_COMMIT();
        CP_WAIT0();
        __syncthreads();

        if (pj <= 1) {
            const int mt = wid & 3, ch = wid >> 2, ar = mt * 16;
            #pragma unroll
            for (int kc = 0; kc < 4; kc++) {
                const int kp = kc * 8;
                uint32_t ah[4] = { xph[(ar + g) * 36 + kp + q], xph[(ar + g + 8) * 36 + kp + q],
                                   xph[(ar + g) * 36 + kp + q + 4], xph[(ar + g + 8) * 36 + kp + q + 4] };
                uint32_t al[4] = { xpl[(ar + g) * 36 + kp + q], xpl[(ar + g + 8) * 36 + kp + q],
                                   xpl[(ar + g) * 36 + kp + q + 4], xpl[(ar + g + 8) * 36 + kp + q + 4] };
                #pragma unroll
                for (int nc = 0; nc < 8; nc++) {
                    const int br = (ch * 64 + nc * 8 + g) * 36 + kp;
                    uint32_t bh[2] = { wh[br + q], wh[br + q + 4] };
                    uint32_t bl[2] = { wl[br + q], wl[br + q + 4] };
                    mma16(ds[nc], ah, bh);
                    mma16(ds[nc], ah, bl);
                    mma16(ds[nc], al, bh);
                }
            }
        } else {
            const int ar = wid * 16;
            #pragma unroll
            for (int kc = 0; kc < 4; kc++) {
                const int kp = kc * 8;
                uint32_t ah[4] = { wh[(ar + g) * 36 + kp + q], wh[(ar + g + 8) * 36 + kp + q],
                                   wh[(ar + g) * 36 + kp + q + 4], wh[(ar + g + 8) * 36 + kp + q + 4] };
                uint32_t al[4] = { wl[(ar + g) * 36 + kp + q], wl[(ar + g + 8) * 36 + kp + q],
                                   wl[(ar + g) * 36 + kp + q + 4], wl[(ar + g + 8) * 36 + kp + q + 4] };
                #pragma unroll
                for (int nc = 0; nc < 8; nc++) {
                    const int br = (nc * 8 + g) * 36 + kp;
                    uint32_t bh[2] = { xph[br + q], xph[br + q + 4] };
                    uint32_t bl[2] = { xpl[br + q], xpl[br + q + 4] };
                    mma16(ds[nc], ah, bh);
                    mma16(ds[nc], ah, bl);
                    mma16(ds[nc], al, bh);
                }
            }
        }
    }

    if (pj <= 1) {
        uint32_t* ph = (pj == 0) ? &g_qh[b][0][0] : &g_kh[b][0][0];
        uint32_t* pl = (pj == 0) ? &g_ql[b][0][0] : &g_kl[b][0][0];
        const int mt = wid & 3, ch = wid >> 2;
        const int nr0 = n0g + mt * 16 + g, nr1 = nr0 + 8;
        #pragma unroll
        for (int nc = 0; nc < 8; nc++) {
            const int co0 = ch * 64 + nc * 8 + 2 * q;
            const float b0 = bs[co0], b1 = bs[co0 + 1];
            float v0 = ds[nc][0] + b0, v1 = ds[nc][1] + b1;
            float v2 = ds[nc][2] + b0, v3 = ds[nc][3] + b1;
            uint32_t h0 = bfp2(v0, v1), h1 = bfp2(v2, v3);
            uint32_t l0 = bfp2(v0 - blo(h0), v1 - bhi(h0));
            uint32_t l1 = bfp2(v2 - blo(h1), v3 - bhi(h1));
            const int pr = ch * 32 + nc * 4 + q;
            ph[(size_t)nr0 * 64 + pr] = h0;  pl[(size_t)nr0 * 64 + pr] = l0;
            ph[(size_t)nr1 * 64 + pr] = h1;  pl[(size_t)nr1 * 64 + pr] = l1;
        }
    } else {
        float* outp = &g_v[b][0][0];
        const int c0 = wid * 16 + g, c1 = c0 + 8;
        const float b0 = bs[c0], b1 = bs[c1];
        #pragma unroll
        for (int nc = 0; nc < 8; nc++) {
            const int n = n0g + nc * 8 + 2 * q;
            *(float2*)&outp[(size_t)c0 * NPIX + n] = make_float2(
                __uint_as_float(tf32r(ds[nc][0] + b0)), __uint_as_float(tf32r(ds[nc][1] + b0)));
            *(float2*)&outp[(size_t)c1 * NPIX + n] = make_float2(
                __uint_as_float(tf32r(ds[nc][2] + b1)), __uint_as_float(tf32r(ds[nc][3] + b1)));
        }
    }
}

// ============================================================================
// Kernel 2: attention (unchanged — measured at tensor-pipe floor).
// ============================================================================
#define QP_STRIDE 68
#define SM_QH 0
#define SM_QL (128 * QP_STRIDE)
#define SM_ST (2 * 128 * QP_STRIDE)
#define STG   (2 * 64 * QP_STRIDE + 128 * QP_STRIDE)
#define ATTN_SMEM_W (SM_ST + 2 * STG)            // 52224 u32 = 208896 B

__global__ __launch_bounds__(256, 1) void attn_mma_kernel()
{
    extern __shared__ uint32_t smw[];
    uint32_t* Qh2 = smw + SM_QH;
    uint32_t* Ql2 = smw + SM_QL;
    const uint32_t smb = (uint32_t)__cvta_generic_to_shared(smw);

    const int tid = threadIdx.x, wid = tid >> 5, lane = tid & 31;
    const int g = lane >> 2, q = lane & 3;
    const int b = blockIdx.y, i0g = blockIdx.x * 128;
    const int iw = wid * 16;

    {
        const uint32_t base = smb + 4u * SM_ST;
        const uint32_t* sKh = &g_kh[b][0][0];
        const uint32_t* sKl = &g_kl[b][0][0];
        const float*    sV  = &g_v[b][0][0];
        #pragma unroll
        for (int v = 0; v < 4; v++) {
            int id = tid + v * 256, j = id >> 4, ch = (id & 15) * 4;
            cpa16(base + 4u * (j * QP_STRIDE + ch), sKh + j * 64 + ch);
        }
        #pragma unroll
        for (int v = 0; v < 4; v++) {
            int id = tid + v * 256, j = id >> 4, ch = (id & 15) * 4;
            cpa16(base + 4u * (64 * QP_STRIDE + j * QP_STRIDE + ch), sKl + j * 64 + ch);
        }
        #pragma unroll
        for (int v = 0; v < 8; v++) {
            int id = tid + v * 256, c = id >> 4, ch = (id & 15) * 4;
            cpa16(base + 4u * (128 * QP_STRIDE + c * QP_STRIDE + ch), sV + (size_t)c * NPIX + ch);
        }
        CP_COMMIT();
    }
    {
        const uint32_t* sQh = &g_qh[b][i0g][0];
        const uint32_t* sQl = &g_ql[b][i0g][0];
        #pragma unroll
        for (int v = 0; v < 8; v++) {
            int id = tid + v * 256, i = id >> 4, ch = (id & 15) * 4;
            *(uint4*)&Qh2[i * QP_STRIDE + ch] = *(const uint4*)&sQh[i * 64 + ch];
            *(uint4*)&Ql2[i * QP_STRIDE + ch] = *(const uint4*)&sQl[i * 64 + ch];
        }
    }

    float o[16][4];
    #pragma unroll
    for (int n = 0; n < 16; n++)
        #pragma unroll
        for (int r = 0; r < 4; r++) o[n][r] = 0.f;
    float ls0 = 0.f, ls1 = 0.f;

    for (int t = 0; t < 64; t++) {
        const int s = t & 1;
        CP_WAIT0();
        __syncthreads();

        if (t < 63) {
            const int j1 = (t + 1) * 64;
            const uint32_t base = smb + 4u * (SM_ST + (s ^ 1) * STG);
            const uint32_t* sKh = &g_kh[b][j1][0];
            const uint32_t* sKl = &g_kl[b][j1][0];
            const float*    sV  = &g_v[b][0][j1];
            #pragma unroll
            for (int v = 0; v < 4; v++) {
                int id = tid + v * 256, j = id >> 4, ch = (id & 15) * 4;
                cpa16(base + 4u * (j * QP_STRIDE + ch), sKh + j * 64 + ch);
            }
            #pragma unroll
            for (int v = 0; v < 4; v++) {
                int id = tid + v * 256, j = id >> 4, ch = (id & 15) * 4;
                cpa16(base + 4u * (64 * QP_STRIDE + j * QP_STRIDE + ch), sKl + j * 64 + ch);
            }
            #pragma unroll
            for (int v = 0; v < 8; v++) {
                int id = tid + v * 256, c = id >> 4, ch = (id & 15) * 4;
                cpa16(base + 4u * (128 * QP_STRIDE + c * QP_STRIDE + ch), sV + (size_t)c * NPIX + ch);
            }
            CP_COMMIT();
        }

        uint32_t* Kh2 = smw + SM_ST + s * STG;
        uint32_t* Kl2 = Kh2 + 64 * QP_STRIDE;
        float*    Vs  = (float*)(Kh2 + 128 * QP_STRIDE);

        float ds[8][4];
        #pragma unroll
        for (int n = 0; n < 8; n++)
            #pragma unroll
            for (int r = 0; r < 4; r++) ds[n][r] = 0.f;

        #pragma unroll
        for (int kc = 0; kc < 8; kc++) {
            const int kp = kc * 8;
            const int ra = (iw + g) * QP_STRIDE + kp + q;
            const int rb = (iw + g + 8) * QP_STRIDE + kp + q;
            uint32_t ah[4] = { Qh2[ra], Qh2[rb], Qh2[ra + 4], Qh2[rb + 4] };
            uint32_t al[4] = { Ql2[ra], Ql2[rb], Ql2[ra + 4], Ql2[rb + 4] };
            #pragma unroll
            for (int n = 0; n < 8; n++) {
                const int kb = (n * 8 + g) * QP_STRIDE + kp + q;
                uint32_t bh[2] = { Kh2[kb], Kh2[kb + 4] };
                uint32_t bl[2] = { Kl2[kb], Kl2[kb + 4] };
                mma16(ds[n], ah, bh);
                mma16(ds[n], ah, bl);
                mma16(ds[n], al, bh);
            }
        }

        #pragma unroll
        for (int n = 0; n < 8; n++) {
            float p0 = pexp30(ds[n][0]), p1 = pexp30(ds[n][1]);
            float p2 = pexp30(ds[n][2]), p3 = pexp30(ds[n][3]);
            ds[n][0] = p0; ds[n][1] = p1; ds[n][2] = p2; ds[n][3] = p3;
            ls0 += p0 + p1;
            ls1 += p2 + p3;
        }

        const int csel = q & 1;
        const int src1 = (lane & ~3) | (q >> 1);
        const int src2 = src1 + 2;
        #pragma unroll
        for (int jk = 0; jk < 8; jk++) {
            float t0 = __shfl_sync(0xffffffffu, ds[jk][0], src1);
            float t1 = __shfl_sync(0xffffffffu, ds[jk][1], src1);
            float t2 = __shfl_sync(0xffffffffu, ds[jk][2], src1);
            float t3 = __shfl_sync(0xffffffffu, ds[jk][3], src1);
            float u0 = __shfl_sync(0xffffffffu, ds[jk][0], src2);
            float u1 = __shfl_sync(0xffffffffu, ds[jk][1], src2);
            float u2 = __shfl_sync(0xffffffffu, ds[jk][2], src2);
            float u3 = __shfl_sync(0xffffffffu, ds[jk][3], src2);
            uint32_t pa[4] = { __float_as_uint(csel ? t1 : t0),
                               __float_as_uint(csel ? t3 : t2),
                               __float_as_uint(csel ? u1 : u0),
                               __float_as_uint(csel ? u3 : u2) };
            const int jb = jk * 8;
            #pragma unroll
            for (int nc = 0; nc < 16; nc++) {
                uint32_t vb[2] = { __float_as_uint(Vs[(nc * 8 + g) * QP_STRIDE + jb + q]),
                                   __float_as_uint(Vs[(nc * 8 + g) * QP_STRIDE + jb + q + 4]) };
                mma8(o[nc], pa, vb);
            }
        }
    }

    ls0 += __shfl_xor_sync(0xffffffffu, ls0, 1);
    ls0 += __shfl_xor_sync(0xffffffffu, ls0, 2);
    ls1 += __shfl_xor_sync(0xffffffffu, ls1, 1);
    ls1 += __shfl_xor_sync(0xffffffffu, ls1, 2);
    const float inv0 = 1.f / ls0, inv1 = 1.f / ls1;
    const int r0 = i0g + iw + g, r1 = r0 + 8;
    #pragma unroll
    for (int nc = 0; nc < 16; nc++) {
        const int cc = nc * 8 + 2 * q;
        *(float2*)&g_att[b][r0][cc] = make_float2(o[nc][0] * inv0, o[nc][1] * inv0);
        *(float2*)&g_att[b][r1][cc] = make_float2(o[nc][2] * inv1, o[nc][3] * inv1);
    }
}

// ============================================================================
// Kernel 3: W conv, tiles [64 o x 128 n], 3-term (plain launch bounds).
// ============================================================================
#define WATH 0                           // att hi [128 n][68]
#define WATL 8704
#define WWH  17408                       // W hi [64 o][68]
#define WWL  21760
#define WBS  26112
#define WCONV_SMEM_W (WBS + 64)          // 26176 u32 = 104704 B

__global__ __launch_bounds__(256) void wconv_mma_kernel(
    const float* __restrict__ x, const float* __restrict__ Wb,
    float* __restrict__ out)
{
    extern __shared__ uint32_t smu[];
    uint32_t* ath = smu + WATH;
    uint32_t* atl = smu + WATL;
    uint32_t* wwh = smu + WWH;
    uint32_t* wwl = smu + WWL;
    float*    bs  = (float*)(smu + WBS);

    const int b = blockIdx.z, og0 = blockIdx.y * 64, gn0 = blockIdx.x * 128;
    const int tid = threadIdx.x, wid = tid >> 5, lane = tid & 31;
    const int g = lane >> 2, q = lane & 3;
    if (tid < 64) bs[tid] = Wb[og0 + tid];

    const float* attb = &g_att[b][gn0][0];
    #pragma unroll
    for (int v = 0; v < 16; v++) {
        int id = tid + v * 256, n = id >> 5, c4 = (id & 31) * 4;
        float4 a = *(const float4*)&attb[(size_t)n * CI + c4];
        uint32_t h0 = bfp2(a.x, a.y), h1 = bfp2(a.z, a.w);
        uint32_t l0 = bfp2(a.x - blo(h0), a.y - bhi(h0));
        uint32_t l1 = bfp2(a.z - blo(h1), a.w - bhi(h1));
        const int p = c4 >> 1;
        *(uint2*)&ath[n * 68 + p] = make_uint2(h0, h1);
        *(uint2*)&atl[n * 68 + p] = make_uint2(l0, l1);
    }
    #pragma unroll
    for (int v = 0; v < 4; v++) {
        int id = tid + v * 256, o = id >> 4, p4 = (id & 15) * 4;
        *(uint4*)&wwh[o * 68 + p4] = *(const uint4*)&g_WWh[og0 + o][p4];
        *(uint4*)&wwl[o * 68 + p4] = *(const uint4*)&g_WWl[og0 + o][p4];
    }
    __syncthreads();

    const int mt = wid & 3, nh = wid >> 2, ar = mt * 16;
    float ds[8][4];
    #pragma unroll
    for (int n = 0; n < 8; n++)
        #pragma unroll
        for (int r = 0; r < 4; r++) ds[n][r] = 0.f;

    #pragma unroll
    for (int kc = 0; kc < 8; kc++) {
        const int kp = kc * 8;
        uint32_t ah[4] = { wwh[(ar + g) * 68 + kp + q], wwh[(ar + g + 8) * 68 + kp + q],
                           wwh[(ar + g) * 68 + kp + q + 4], wwh[(ar + g + 8) * 68 + kp + q + 4] };
        uint32_t al[4] = { wwl[(ar + g) * 68 + kp + q], wwl[(ar + g + 8) * 68 + kp + q],
                           wwl[(ar + g) * 68 + kp + q + 4], wwl[(ar + g + 8) * 68 + kp + q + 4] };
        #pragma unroll
        for (int nc = 0; nc < 8; nc++) {
            const int br = (nh * 64 + nc * 8 + g) * 68 + kp;
            uint32_t bh[2] = { ath[br + q], ath[br + q + 4] };
            uint32_t bl[2] = { atl[br + q], atl[br + q + 4] };
            mma16(ds[nc], ah, bh);
            mma16(ds[nc], ah, bl);
            mma16(ds[nc], al, bh);
        }
    }

    const int o0 = og0 + ar + g, o1 = o0 + 8;
    const float b0 = bs[ar + g], b1 = bs[ar + g + 8];
    #pragma unroll
    for (int nc = 0; nc < 8; nc++) {
        const int n = gn0 + nh * 64 + nc * 8 + 2 * q;
        size_t off0 = ((size_t)b * CIN + o0) * NPIX + n;
        size_t off1 = ((size_t)b * CIN + o1) * NPIX + n;
        float2 x0 = *(const float2*)&x[off0];
        float2 x1 = *(const float2*)&x[off1];
        *(float2*)&out[off0] = make_float2(ds[nc][0] + b0 + x0.x, ds[nc][1] + b0 + x0.y);
        *(float2*)&out[off1] = make_float2(ds[nc][2] + b1 + x1.x, ds[nc][3] + b1 + x1.y);
    }
}

// ============================================================================
extern "C" void kernel_launch(void* const* d_in, const int* in_sizes, int n_in,
                              void* d_out, int out_size)
{
    const float* x    = (const float*)d_in[0];
    const float* g_w  = (const float*)d_in[1];
    const float* g_b  = (const float*)d_in[2];
    const float* th_w = (const float*)d_in[3];
    const float* th_b = (const float*)d_in[4];
    const float* ph_w = (const float*)d_in[5];
    const float* ph_b = (const float*)d_in[6];
    const float* W_w  = (const float*)d_in[7];
    const float* W_b  = (const float*)d_in[8];
    float* out = (float*)d_out;

    prep_kernel<<<64, 256>>>(th_w, ph_w, g_w, W_w);
    prep2_kernel<<<dim3(64, 8), 256>>>(x);

    const int proj_smem = PROJ_SMEM_W * 4;     // 55808 B
    cudaFuncSetAttribute(proj_mma_kernel,
                         cudaFuncAttributeMaxDynamicSharedMemorySize, proj_smem);
    proj_mma_kernel<<<dim3(64, 3, 8), 256, proj_smem>>>(th_b, ph_b, g_b);

    const int attn_smem = ATTN_SMEM_W * 4;     // 208896 B
    cudaFuncSetAttribute(attn_mma_kernel,
                         cudaFuncAttributeMaxDynamicSharedMemorySize, attn_smem);
    attn_mma_kernel<<<dim3(32, 8), 256, attn_smem>>>();

    const int wconv_smem = WCONV_SMEM_W * 4;   // 104704 B
    cudaFuncSetAttribute(wconv_mma_kernel,
                         cudaFuncAttributeMaxDynamicSharedMemorySize, wconv_smem);
    wconv_mma_kernel<<<dim3(32, 4, 8), 256, wconv_smem>>>(x, W_b, out);
}